// round 1
// baseline (speedup 1.0000x reference)
#include <cuda_runtime.h>
#include <math.h>

#define BATCH 256
#define TOUT  36
#define SIN   96
#define DIM   1024
#define HID   1024
#define NLAY  2

// ---------------- scratch (device globals: allocation-free) ----------------
__device__ float g_h[NLAY * BATCH * HID];       // recurrent hidden state
__device__ float g_logits[BATCH * SIN];
__device__ float g_aw[BATCH * SIN];
__device__ float g_wenc[BATCH * HID];
__device__ float g_xc[BATCH * DIM];
__device__ float g_gi[BATCH * 3 * HID];
__device__ float g_gh[BATCH * 3 * HID];
__device__ float g_tmp[BATCH * DIM];

// ---------------- generic fp32 GEMM: C = act(A @ W^T + bias) ----------------
// A row m: first K0 columns from A0 (row stride lda0), remaining K-K0 from A1
// (row stride lda1). W is (N,K) row-major. M is always 256 here (grid.y = 8).
// BM=32, BN=64, BK=32, 64 threads, 8x4 register tile per thread.
__global__ __launch_bounds__(64) void gemm64(
    const float* __restrict__ A0, int lda0, int K0,
    const float* __restrict__ A1, int lda1,
    const float* __restrict__ W, const float* __restrict__ bias,
    float* __restrict__ C, int ldc, int N, int K, int act)
{
    const int BM = 32, BN = 64, BK = 32;
    __shared__ float As[BK][BM + 1];
    __shared__ float Ws[BK][BN + 1];

    int tid = threadIdx.x;
    int tr = tid >> 4;    // 0..3  -> 8 rows each
    int tc = tid & 15;    // 0..15 -> 4 cols each
    int rowBase = blockIdx.y * BM;
    int colBase = blockIdx.x * BN;

    float acc[8][4];
#pragma unroll
    for (int i = 0; i < 8; i++)
#pragma unroll
        for (int j = 0; j < 4; j++) acc[i][j] = 0.f;

    for (int k0 = 0; k0 < K; k0 += BK) {
        // A slab: 32 rows x 32 k  (4 x float4 per thread), stored transposed
#pragma unroll
        for (int i = 0; i < 4; i++) {
            int idx = tid + i * 64;        // 0..255
            int r   = idx >> 3;            // 0..31
            int c4  = (idx & 7) * 4;       // 0,4,...,28
            int kg  = k0 + c4;
            int rg  = rowBase + r;
            const float* src;
            int kk;
            if (kg < K0) { src = A0 + (size_t)rg * lda0; kk = kg; }
            else         { src = A1 + (size_t)rg * lda1; kk = kg - K0; }
            float4 v = *reinterpret_cast<const float4*>(src + kk);
            As[c4 + 0][r] = v.x; As[c4 + 1][r] = v.y;
            As[c4 + 2][r] = v.z; As[c4 + 3][r] = v.w;
        }
        // W slab: 64 rows x 32 k  (8 x float4 per thread), stored transposed
#pragma unroll
        for (int i = 0; i < 8; i++) {
            int idx = tid + i * 64;        // 0..511
            int r   = idx >> 3;            // 0..63
            int c4  = (idx & 7) * 4;
            int ng  = colBase + r;
            float4 v = make_float4(0.f, 0.f, 0.f, 0.f);
            if (ng < N)
                v = *reinterpret_cast<const float4*>(W + (size_t)ng * K + k0 + c4);
            Ws[c4 + 0][r] = v.x; Ws[c4 + 1][r] = v.y;
            Ws[c4 + 2][r] = v.z; Ws[c4 + 3][r] = v.w;
        }
        __syncthreads();
#pragma unroll
        for (int k = 0; k < BK; k++) {
            float a[8], w[4];
#pragma unroll
            for (int i = 0; i < 8; i++) a[i] = As[k][tr * 8 + i];
#pragma unroll
            for (int j = 0; j < 4; j++) w[j] = Ws[k][tc * 4 + j];
#pragma unroll
            for (int i = 0; i < 8; i++)
#pragma unroll
                for (int j = 0; j < 4; j++)
                    acc[i][j] = fmaf(a[i], w[j], acc[i][j]);
        }
        __syncthreads();
    }

#pragma unroll
    for (int j = 0; j < 4; j++) {
        int ng = colBase + tc * 4 + j;
        if (ng >= N) continue;
        float bv = bias ? bias[ng] : 0.f;
#pragma unroll
        for (int i = 0; i < 8; i++) {
            int rg = rowBase + tr * 8 + i;
            float v = acc[i][j] + bv;
            if (act == 1) v = fmaxf(v, 0.f);
            C[(size_t)rg * ldc + ng] = v;
        }
    }
}

// ---------------- softmax over S_IN=96, writes aw scratch + d_out slice -----
__global__ void softmax_kernel(const float* __restrict__ logits,
                               float* __restrict__ aw,
                               float* __restrict__ out_attn, int t)
{
    __shared__ float sm[128];
    int b = blockIdx.x, tid = threadIdx.x;
    float v = (tid < SIN) ? logits[b * SIN + tid] : -1e30f;
    sm[tid] = v; __syncthreads();
    for (int s = 64; s > 0; s >>= 1) {
        if (tid < s) sm[tid] = fmaxf(sm[tid], sm[tid + s]);
        __syncthreads();
    }
    float mx = sm[0]; __syncthreads();
    float e = (tid < SIN) ? expf(v - mx) : 0.f;
    sm[tid] = e; __syncthreads();
    for (int s = 64; s > 0; s >>= 1) {
        if (tid < s) sm[tid] += sm[tid + s];
        __syncthreads();
    }
    float inv = 1.f / sm[0];
    if (tid < SIN) {
        float a = e * inv;
        aw[b * SIN + tid] = a;
        out_attn[(size_t)b * TOUT * SIN + (size_t)t * SIN + tid] = a;
    }
}

// ---------------- w_enc[b,h] = sum_s aw[b,s] * enc[b,s,h] ------------------
__global__ void wenc_kernel(const float* __restrict__ aw,
                            const float* __restrict__ enc,
                            float* __restrict__ wenc)
{
    __shared__ float a[SIN];
    int b = blockIdx.y;
    int h = blockIdx.x * 256 + threadIdx.x;
    if (threadIdx.x < SIN) a[threadIdx.x] = aw[b * SIN + threadIdx.x];
    __syncthreads();
    const float* e = enc + (size_t)b * SIN * HID + h;
    float acc = 0.f;
#pragma unroll 8
    for (int s = 0; s < SIN; s++) acc = fmaf(a[s], e[(size_t)s * HID], acc);
    wenc[b * HID + h] = acc;
}

// ---------------- GRU gate combine (in-place hidden update) ----------------
__global__ void gate_kernel(const float* __restrict__ gi,
                            const float* __restrict__ gh,
                            float* __restrict__ h)
{
    int idx = blockIdx.x * 256 + threadIdx.x;   // b*HID + j
    int b = idx >> 10;
    int j = idx & 1023;
    const float* gib = gi + (size_t)b * 3 * HID;
    const float* ghb = gh + (size_t)b * 3 * HID;
    float ir = gib[j], iz = gib[HID + j], in_ = gib[2 * HID + j];
    float hr = ghb[j], hz = ghb[HID + j], hn  = ghb[2 * HID + j];
    float r = 1.f / (1.f + expf(-(ir + hr)));
    float z = 1.f / (1.f + expf(-(iz + hz)));
    float n = tanhf(in_ + r * hn);
    float ho = h[idx];
    h[idx] = (1.f - z) * n + z * ho;
}

__global__ void copy_kernel(const float* __restrict__ src,
                            float* __restrict__ dst, int n)
{
    int i = blockIdx.x * 256 + threadIdx.x;
    if (i < n) dst[i] = src[i];
}

// ---------------- host orchestration ----------------
extern "C" void kernel_launch(void* const* d_in, const int* in_sizes, int n_in,
                              void* d_out, int out_size)
{
    const float* target = (const float*)d_in[0];
    const float* hidden = (const float*)d_in[1];
    const float* enc    = (const float*)d_in[2];
    const float* attn_W = (const float*)d_in[3];
    const float* attn_b = (const float*)d_in[4];
    const float* comb_W = (const float*)d_in[5];
    const float* comb_b = (const float*)d_in[6];
    const float* W_ih   = (const float*)d_in[7];
    const float* W_hh   = (const float*)d_in[8];
    const float* b_ih   = (const float*)d_in[9];
    const float* b_hh   = (const float*)d_in[10];
    const float* out1_W = (const float*)d_in[11];
    const float* out1_b = (const float*)d_in[12];
    const float* out2_W = (const float*)d_in[13];
    const float* out2_b = (const float*)d_in[14];

    float* out   = (float*)d_out;
    float* out_y = out;                                    // (B, T, D)
    float* out_h = out + (size_t)BATCH * TOUT * DIM;       // (L, B, H)
    float* out_a = out_h + (size_t)NLAY * BATCH * HID;     // (B, T, S_IN)

    float *h_, *logits, *aw, *wenc, *xc, *gi, *gh, *tmp;
    cudaGetSymbolAddress((void**)&h_,     g_h);
    cudaGetSymbolAddress((void**)&logits, g_logits);
    cudaGetSymbolAddress((void**)&aw,     g_aw);
    cudaGetSymbolAddress((void**)&wenc,   g_wenc);
    cudaGetSymbolAddress((void**)&xc,     g_xc);
    cudaGetSymbolAddress((void**)&gi,     g_gi);
    cudaGetSymbolAddress((void**)&gh,     g_gh);
    cudaGetSymbolAddress((void**)&tmp,    g_tmp);

    const int ldx = TOUT * DIM;   // target row stride
    const dim3 gN96(2, 8),  gN1024(16, 8), gN3072(48, 8);

    // init recurrent state from input hidden
    copy_kernel<<<(NLAY * BATCH * HID) / 256, 256>>>(hidden, h_, NLAY * BATCH * HID);

    for (int t = 0; t < TOUT; t++) {
        const float* xt = target + (size_t)t * DIM;

        // attn logits = cat(x, h[last]) @ attn_W^T + attn_b     (256 x 96, K=2048)
        gemm64<<<gN96, 64>>>(xt, ldx, DIM, h_ + (NLAY - 1) * BATCH * HID, HID,
                             attn_W, attn_b, logits, SIN, SIN, DIM + HID, 0);
        softmax_kernel<<<BATCH, 128>>>(logits, aw, out_a, t);
        wenc_kernel<<<dim3(HID / 256, BATCH), 256>>>(aw, enc, wenc);

        // xc = relu(cat(x, w_enc) @ comb_W^T + comb_b)          (256 x 1024, K=2048)
        gemm64<<<gN1024, 64>>>(xt, ldx, DIM, wenc, HID,
                               comb_W, comb_b, xc, DIM, DIM, DIM + HID, 1);

        // GRU layer 0
        gemm64<<<gN3072, 64>>>(xc, DIM, DIM, nullptr, 0,
                               W_ih, b_ih, gi, 3 * HID, 3 * HID, DIM, 0);
        gemm64<<<gN3072, 64>>>(h_, HID, HID, nullptr, 0,
                               W_hh, b_hh, gh, 3 * HID, 3 * HID, HID, 0);
        gate_kernel<<<(BATCH * HID) / 256, 256>>>(gi, gh, h_);

        // GRU layer 1 (input = updated layer-0 hidden)
        gemm64<<<gN3072, 64>>>(h_, HID, HID, nullptr, 0,
                               W_ih + (size_t)3 * HID * DIM, b_ih + 3 * HID,
                               gi, 3 * HID, 3 * HID, HID, 0);
        gemm64<<<gN3072, 64>>>(h_ + BATCH * HID, HID, HID, nullptr, 0,
                               W_hh + (size_t)3 * HID * HID, b_hh + 3 * HID,
                               gh, 3 * HID, 3 * HID, HID, 0);
        gate_kernel<<<(BATCH * HID) / 256, 256>>>(gi, gh, h_ + BATCH * HID);

        // output head: y = (h1 @ out1_W^T + b1) @ out2_W^T + b2
        gemm64<<<gN1024, 64>>>(h_ + BATCH * HID, HID, HID, nullptr, 0,
                               out1_W, out1_b, tmp, DIM, DIM, HID, 0);
        gemm64<<<gN1024, 64>>>(tmp, DIM, DIM, nullptr, 0,
                               out2_W, out2_b, out_y + (size_t)t * DIM, ldx,
                               DIM, DIM, 0);
    }

    // final hidden state
    copy_kernel<<<(NLAY * BATCH * HID) / 256, 256>>>(h_, out_h, NLAY * BATCH * HID);
}

// round 3
// speedup vs baseline: 1.7209x; 1.7209x over previous
#include <cuda_runtime.h>
#include <cuda_bf16.h>
#include <math.h>

#define BATCH 256
#define TOUT  36
#define SIN   96
#define DIM   1024
#define HID   1024
#define NLAY  2

typedef __nv_bfloat16 bf16;

#define BH      (BATCH * HID)            // 262144
#define XOFF    ((size_t)BATCH * TOUT * DIM)
#define WIH_OFF ((size_t)NLAY * 3 * HID * DIM)
#define WHH_OFF ((size_t)NLAY * 3 * HID * HID)

// ---------------- scratch (device globals: allocation-free) ----------------
__device__ float g_h[NLAY * BATCH * HID];
__device__ bf16  g_hd0[2 * BATCH * HID];
__device__ bf16  g_hd1[2 * BATCH * HID];
__device__ bf16  g_xd[2 * (size_t)BATCH * TOUT * DIM];
__device__ bf16  g_xcd[2 * BATCH * DIM];
__device__ bf16  g_wencd[2 * BATCH * HID];
__device__ bf16  g_tmpd[2 * BATCH * DIM];
__device__ float g_logits[BATCH * SIN];
__device__ float g_aw[BATCH * SIN];
__device__ float g_gi[BATCH * 3 * HID];
__device__ float g_gh[BATCH * 3 * HID];
// decomposed weights (hi block, then lo block)
__device__ bf16 g_attnWd[2 * SIN * (DIM + HID)];
__device__ bf16 g_combWd[2 * DIM * (DIM + HID)];
__device__ bf16 g_Wihd[2 * NLAY * 3 * HID * DIM];
__device__ bf16 g_Whhd[2 * NLAY * 3 * HID * HID];
__device__ bf16 g_out1d[2 * DIM * HID];
__device__ bf16 g_out2d[2 * DIM * DIM];

// ---------------- helpers ----------------
__device__ __forceinline__ void dec2(float v, bf16& hi, bf16& lo) {
    hi = __float2bfloat16(v);
    lo = __float2bfloat16(v - __bfloat162float(hi));
}

__device__ __forceinline__ void mma_bf16(float c[4], const unsigned a[4], const unsigned b[2]) {
    asm volatile(
        "mma.sync.aligned.m16n8k16.row.col.f32.bf16.bf16.f32 "
        "{%0,%1,%2,%3},{%4,%5,%6,%7},{%8,%9},{%0,%1,%2,%3};\n"
        : "+f"(c[0]), "+f"(c[1]), "+f"(c[2]), "+f"(c[3])
        : "r"(a[0]), "r"(a[1]), "r"(a[2]), "r"(a[3]), "r"(b[0]), "r"(b[1]));
}

// ---------------- weight / input decomposition ----------------
__global__ void decomp_kernel(const float* __restrict__ src, bf16* __restrict__ dst,
                              size_t off, int n)
{
    int i = blockIdx.x * 256 + threadIdx.x;
    if (i < n) {
        bf16 hi, lo;
        dec2(src[i], hi, lo);
        dst[i] = hi;
        dst[off + i] = lo;
    }
}

__global__ void init_h_kernel(const float* __restrict__ hidden,
                              float* __restrict__ h,
                              bf16* __restrict__ hd0, bf16* __restrict__ hd1)
{
    int i = blockIdx.x * 256 + threadIdx.x;   // < NLAY*B*H
    float v = hidden[i];
    h[i] = v;
    int l = i >> 18;            // B*H = 2^18
    int j = i & (BH - 1);
    bf16* hd = l ? hd1 : hd0;
    bf16 hi, lo;
    dec2(v, hi, lo);
    hd[j] = hi;
    hd[BH + j] = lo;
}

__global__ void copy_kernel(const float* __restrict__ src, float* __restrict__ dst, int n)
{
    int i = blockIdx.x * 256 + threadIdx.x;
    if (i < n) dst[i] = src[i];
}

// ---------------- tensor-core GEMM: C = act(A @ W^T + bias) ----------------
// A (bf16, decomposed hi/lo): row m -> first K0 cols from A0 (stride lda0),
// rest from A1 (stride lda1); lo part at +aoff. W bf16 (N,K), lo at +woff.
// M = 256 (grid.y = 4, BM=64). BN=64, BK=32. 128 threads, 4 warps (2x2),
// warp tile 32x32 via m16n8k16 bf16 MMA, 3-term error-compensated.
__global__ __launch_bounds__(128) void gemm_tc(
    const bf16* __restrict__ A0, size_t aoff0, int lda0, int K0,
    const bf16* __restrict__ A1, size_t aoff1, int lda1,
    const bf16* __restrict__ Wd, size_t woff,
    const float* __restrict__ bias,
    float* __restrict__ C, int ldc,
    bf16* __restrict__ Cd, size_t cdoff, int ldcd,
    int N, int K, int act)
{
    __shared__ bf16 As[2][64][40];   // [hi/lo][m][k] (pad 40 -> conflict-free)
    __shared__ bf16 Ws[2][64][40];   // [hi/lo][n][k]

    int tid = threadIdx.x, lane = tid & 31, warp = tid >> 5;
    int wm = (warp >> 1) * 32, wn = (warp & 1) * 32;
    int rowBase = blockIdx.y * 64, colBase = blockIdx.x * 64;

    float acc[2][4][4];
#pragma unroll
    for (int mt = 0; mt < 2; mt++)
#pragma unroll
        for (int nt = 0; nt < 4; nt++)
#pragma unroll
            for (int q = 0; q < 4; q++) acc[mt][nt][q] = 0.f;

    for (int k0 = 0; k0 < K; k0 += 32) {
        const bf16* Abase;
        size_t aoff;
        int lda, kk;
        if (k0 < K0) { Abase = A0; aoff = aoff0; lda = lda0; kk = k0; }
        else         { Abase = A1; aoff = aoff1; lda = lda1; kk = k0 - K0; }

        // A slab: 64 rows x 32 k, hi+lo (uint = bf16x2 loads)
#pragma unroll
        for (int i = 0; i < 8; i++) {
            int idx = tid + i * 128;       // 0..1023
            int r = idx >> 4;              // 0..63
            int u = idx & 15;              // k-pair 0..15
            const bf16* ph = Abase + (size_t)(rowBase + r) * lda + kk + u * 2;
            *(unsigned*)&As[0][r][u * 2] = *(const unsigned*)ph;
            *(unsigned*)&As[1][r][u * 2] = *(const unsigned*)(ph + aoff);
        }
        // W slab: 64 n-rows x 32 k, hi+lo, guard n < N
#pragma unroll
        for (int i = 0; i < 8; i++) {
            int idx = tid + i * 128;
            int r = idx >> 4;
            int u = idx & 15;
            int nn = colBase + r;
            unsigned vh = 0, vl = 0;
            if (nn < N) {
                const bf16* pw = Wd + (size_t)nn * K + k0 + u * 2;
                vh = *(const unsigned*)pw;
                vl = *(const unsigned*)(pw + woff);
            }
            *(unsigned*)&Ws[0][r][u * 2] = vh;
            *(unsigned*)&Ws[1][r][u * 2] = vl;
        }
        __syncthreads();

#pragma unroll
        for (int kk16 = 0; kk16 < 32; kk16 += 16) {
            unsigned ah[2][4], al[2][4], bh[4][2], bl[4][2];
            int kc = kk16 + (lane & 3) * 2;
#pragma unroll
            for (int mt = 0; mt < 2; mt++) {
                int r0 = wm + mt * 16 + (lane >> 2);
                ah[mt][0] = *(const unsigned*)&As[0][r0][kc];
                ah[mt][1] = *(const unsigned*)&As[0][r0 + 8][kc];
                ah[mt][2] = *(const unsigned*)&As[0][r0][kc + 8];
                ah[mt][3] = *(const unsigned*)&As[0][r0 + 8][kc + 8];
                al[mt][0] = *(const unsigned*)&As[1][r0][kc];
                al[mt][1] = *(const unsigned*)&As[1][r0 + 8][kc];
                al[mt][2] = *(const unsigned*)&As[1][r0][kc + 8];
                al[mt][3] = *(const unsigned*)&As[1][r0 + 8][kc + 8];
            }
#pragma unroll
            for (int nt = 0; nt < 4; nt++) {
                int n0 = wn + nt * 8 + (lane >> 2);
                bh[nt][0] = *(const unsigned*)&Ws[0][n0][kc];
                bh[nt][1] = *(const unsigned*)&Ws[0][n0][kc + 8];
                bl[nt][0] = *(const unsigned*)&Ws[1][n0][kc];
                bl[nt][1] = *(const unsigned*)&Ws[1][n0][kc + 8];
            }
#pragma unroll
            for (int mt = 0; mt < 2; mt++)
#pragma unroll
                for (int nt = 0; nt < 4; nt++) {
                    mma_bf16(acc[mt][nt], ah[mt], bh[nt]);
                    mma_bf16(acc[mt][nt], ah[mt], bl[nt]);
                    mma_bf16(acc[mt][nt], al[mt], bh[nt]);
                }
        }
        __syncthreads();
    }

    // epilogue
#pragma unroll
    for (int mt = 0; mt < 2; mt++)
#pragma unroll
        for (int nt = 0; nt < 4; nt++) {
            int r0 = rowBase + wm + mt * 16 + (lane >> 2);
            int c0 = colBase + wn + nt * 8 + (lane & 3) * 2;
            if (c0 >= N) continue;   // N is even -> c0+1 also valid when c0<N
            float b0 = bias ? bias[c0] : 0.f;
            float b1 = bias ? bias[c0 + 1] : 0.f;
#pragma unroll
            for (int p = 0; p < 2; p++) {
                int r = r0 + p * 8;
                float v0 = acc[mt][nt][p * 2] + b0;
                float v1 = acc[mt][nt][p * 2 + 1] + b1;
                if (act == 1) { v0 = fmaxf(v0, 0.f); v1 = fmaxf(v1, 0.f); }
                if (C) {
                    C[(size_t)r * ldc + c0] = v0;
                    C[(size_t)r * ldc + c0 + 1] = v1;
                }
                if (Cd) {
                    bf16 h0, l0, h1, l1;
                    dec2(v0, h0, l0);
                    dec2(v1, h1, l1);
                    size_t o = (size_t)r * ldcd + c0;
                    Cd[o] = h0; Cd[o + 1] = h1;
                    Cd[cdoff + o] = l0; Cd[cdoff + o + 1] = l1;
                }
            }
        }
}

// ---------------- softmax over S_IN=96 ----------------
__global__ void softmax_kernel(const float* __restrict__ logits,
                               float* __restrict__ aw,
                               float* __restrict__ out_attn, int t)
{
    __shared__ float sm[128];
    int b = blockIdx.x, tid = threadIdx.x;
    float v = (tid < SIN) ? logits[b * SIN + tid] : -1e30f;
    sm[tid] = v; __syncthreads();
    for (int s = 64; s > 0; s >>= 1) {
        if (tid < s) sm[tid] = fmaxf(sm[tid], sm[tid + s]);
        __syncthreads();
    }
    float mx = sm[0]; __syncthreads();
    float e = (tid < SIN) ? expf(v - mx) : 0.f;
    sm[tid] = e; __syncthreads();
    for (int s = 64; s > 0; s >>= 1) {
        if (tid < s) sm[tid] += sm[tid + s];
        __syncthreads();
    }
    float inv = 1.f / sm[0];
    if (tid < SIN) {
        float a = e * inv;
        aw[b * SIN + tid] = a;
        out_attn[(size_t)b * TOUT * SIN + (size_t)t * SIN + tid] = a;
    }
}

// ---------------- w_enc[b,h] = sum_s aw[b,s] * enc[b,s,h] (writes bf16 hi/lo)
__global__ void wenc_kernel(const float* __restrict__ aw,
                            const float* __restrict__ enc,
                            bf16* __restrict__ wencd)
{
    __shared__ float a[SIN];
    int b = blockIdx.y;
    int h = blockIdx.x * 256 + threadIdx.x;
    if (threadIdx.x < SIN) a[threadIdx.x] = aw[b * SIN + threadIdx.x];
    __syncthreads();
    const float* e = enc + (size_t)b * SIN * HID + h;
    float acc = 0.f;
#pragma unroll 8
    for (int s = 0; s < SIN; s++) acc = fmaf(a[s], e[(size_t)s * HID], acc);
    bf16 hi, lo;
    dec2(acc, hi, lo);
    int idx = b * HID + h;
    wencd[idx] = hi;
    wencd[BH + idx] = lo;
}

// ---------------- GRU gate combine (updates fp32 h + bf16 decomposition) ---
__global__ void gate_kernel(const float* __restrict__ gi,
                            const float* __restrict__ gh,
                            float* __restrict__ h,
                            bf16* __restrict__ hd)
{
    int idx = blockIdx.x * 256 + threadIdx.x;   // b*HID + j
    int b = idx >> 10;
    int j = idx & 1023;
    const float* gib = gi + (size_t)b * 3 * HID;
    const float* ghb = gh + (size_t)b * 3 * HID;
    float ir = gib[j], iz = gib[HID + j], in_ = gib[2 * HID + j];
    float hr = ghb[j], hz = ghb[HID + j], hn  = ghb[2 * HID + j];
    float r = 1.f / (1.f + expf(-(ir + hr)));
    float z = 1.f / (1.f + expf(-(iz + hz)));
    float n = tanhf(in_ + r * hn);
    float ho = h[idx];
    float v = (1.f - z) * n + z * ho;
    h[idx] = v;
    bf16 hi, lo;
    dec2(v, hi, lo);
    hd[idx] = hi;
    hd[BH + idx] = lo;
}

// ---------------- host orchestration ----------------
extern "C" void kernel_launch(void* const* d_in, const int* in_sizes, int n_in,
                              void* d_out, int out_size)
{
    const float* target = (const float*)d_in[0];
    const float* hidden = (const float*)d_in[1];
    const float* enc    = (const float*)d_in[2];
    const float* attn_W = (const float*)d_in[3];
    const float* attn_b = (const float*)d_in[4];
    const float* comb_W = (const float*)d_in[5];
    const float* comb_b = (const float*)d_in[6];
    const float* W_ih   = (const float*)d_in[7];
    const float* W_hh   = (const float*)d_in[8];
    const float* b_ih   = (const float*)d_in[9];
    const float* b_hh   = (const float*)d_in[10];
    const float* out1_W = (const float*)d_in[11];
    const float* out1_b = (const float*)d_in[12];
    const float* out2_W = (const float*)d_in[13];
    const float* out2_b = (const float*)d_in[14];

    float* out   = (float*)d_out;
    float* out_y = out;                                    // (B, T, D)
    float* out_h = out + (size_t)BATCH * TOUT * DIM;       // (L, B, H)
    float* out_a = out_h + (size_t)NLAY * BATCH * HID;     // (B, T, S_IN)

    float *h_, *logits, *aw, *gi, *gh;
    bf16 *hd0, *hd1, *xd, *xcd, *wencd, *tmpd;
    bf16 *attnWd, *combWd, *Wihd, *Whhd, *out1d, *out2d;
    cudaGetSymbolAddress((void**)&h_,     g_h);
    cudaGetSymbolAddress((void**)&hd0,    g_hd0);
    cudaGetSymbolAddress((void**)&hd1,    g_hd1);
    cudaGetSymbolAddress((void**)&xd,     g_xd);
    cudaGetSymbolAddress((void**)&xcd,    g_xcd);
    cudaGetSymbolAddress((void**)&wencd,  g_wencd);
    cudaGetSymbolAddress((void**)&tmpd,   g_tmpd);
    cudaGetSymbolAddress((void**)&logits, g_logits);
    cudaGetSymbolAddress((void**)&aw,     g_aw);
    cudaGetSymbolAddress((void**)&gi,     g_gi);
    cudaGetSymbolAddress((void**)&gh,     g_gh);
    cudaGetSymbolAddress((void**)&attnWd, g_attnWd);
    cudaGetSymbolAddress((void**)&combWd, g_combWd);
    cudaGetSymbolAddress((void**)&Wihd,   g_Wihd);
    cudaGetSymbolAddress((void**)&Whhd,   g_Whhd);
    cudaGetSymbolAddress((void**)&out1d,  g_out1d);
    cudaGetSymbolAddress((void**)&out2d,  g_out2d);

    // prologue: decompose weights + target, init hidden
    {
        int n;
        n = SIN * (DIM + HID);
        decomp_kernel<<<(n + 255) / 256, 256>>>(attn_W, attnWd, n, n);
        n = DIM * (DIM + HID);
        decomp_kernel<<<(n + 255) / 256, 256>>>(comb_W, combWd, n, n);
        n = NLAY * 3 * HID * DIM;
        decomp_kernel<<<(n + 255) / 256, 256>>>(W_ih, Wihd, n, n);
        n = NLAY * 3 * HID * HID;
        decomp_kernel<<<(n + 255) / 256, 256>>>(W_hh, Whhd, n, n);
        n = DIM * HID;
        decomp_kernel<<<(n + 255) / 256, 256>>>(out1_W, out1d, n, n);
        n = DIM * DIM;
        decomp_kernel<<<(n + 255) / 256, 256>>>(out2_W, out2d, n, n);
        n = (int)(BATCH * TOUT * DIM);
        decomp_kernel<<<(n + 255) / 256, 256>>>(target, xd, XOFF, n);
        init_h_kernel<<<(NLAY * BH) / 256, 256>>>(hidden, h_, hd0, hd1);
    }

    const int LDX = TOUT * DIM;
    const size_t BD = (size_t)BATCH * DIM;

    for (int t = 0; t < TOUT; t++) {
        const bf16* xt = xd + (size_t)t * DIM;

        // attn logits = cat(x, h1) @ attn_W^T + b    (256 x 96, K=2048)
        gemm_tc<<<dim3(2, 4), 128>>>(xt, XOFF, LDX, DIM,
                                     hd1, BH, HID,
                                     attnWd, (size_t)SIN * (DIM + HID),
                                     attn_b, logits, SIN,
                                     nullptr, 0, 0, SIN, DIM + HID, 0);
        softmax_kernel<<<BATCH, 128>>>(logits, aw, out_a, t);
        wenc_kernel<<<dim3(HID / 256, BATCH), 256>>>(aw, enc, wencd);

        // xc = relu(cat(x, w_enc) @ comb_W^T + b)    (256 x 1024, K=2048) -> decomposed
        gemm_tc<<<dim3(16, 4), 128>>>(xt, XOFF, LDX, DIM,
                                      wencd, BH, HID,
                                      combWd, (size_t)DIM * (DIM + HID),
                                      comb_b, nullptr, 0,
                                      xcd, BD, DIM, DIM, DIM + HID, 1);

        // GRU layer 0
        gemm_tc<<<dim3(48, 4), 128>>>(xcd, BD, DIM, DIM, nullptr, 0, 0,
                                      Wihd, WIH_OFF, b_ih, gi, 3 * HID,
                                      nullptr, 0, 0, 3 * HID, DIM, 0);
        gemm_tc<<<dim3(48, 4), 128>>>(hd0, BH, HID, HID, nullptr, 0, 0,
                                      Whhd, WHH_OFF, b_hh, gh, 3 * HID,
                                      nullptr, 0, 0, 3 * HID, HID, 0);
        gate_kernel<<<BH / 256, 256>>>(gi, gh, h_, hd0);

        // GRU layer 1
        gemm_tc<<<dim3(48, 4), 128>>>(hd0, BH, HID, HID, nullptr, 0, 0,
                                      Wihd + (size_t)3 * HID * DIM, WIH_OFF,
                                      b_ih + 3 * HID, gi, 3 * HID,
                                      nullptr, 0, 0, 3 * HID, HID, 0);
        gemm_tc<<<dim3(48, 4), 128>>>(hd1, BH, HID, HID, nullptr, 0, 0,
                                      Whhd + (size_t)3 * HID * HID, WHH_OFF,
                                      b_hh + 3 * HID, gh, 3 * HID,
                                      nullptr, 0, 0, 3 * HID, HID, 0);
        gate_kernel<<<BH / 256, 256>>>(gi, gh, h_ + BH, hd1);

        // output head
        gemm_tc<<<dim3(16, 4), 128>>>(hd1, BH, HID, HID, nullptr, 0, 0,
                                      out1d, (size_t)DIM * HID, out1_b,
                                      nullptr, 0,
                                      tmpd, BD, DIM, DIM, HID, 0);
        gemm_tc<<<dim3(16, 4), 128>>>(tmpd, BD, DIM, DIM, nullptr, 0, 0,
                                      out2d, (size_t)DIM * DIM, out2_b,
                                      out_y + (size_t)t * DIM, LDX,
                                      nullptr, 0, 0, DIM, DIM, 0);
    }

    copy_kernel<<<(NLAY * BH) / 256, 256>>>(h_, out_h, NLAY * BH);
}

// round 4
// speedup vs baseline: 3.2273x; 1.8753x over previous
#include <cuda_runtime.h>
#include <cuda_bf16.h>
#include <math.h>

#define BATCH 256
#define TOUT  36
#define SIN   96
#define SINP  128          // padded attn N
#define DIM   1024
#define HID   1024
#define NLAY  2

typedef __nv_bfloat16 bf16;

#define BH      (BATCH * HID)
#define XOFF    ((size_t)BATCH * TOUT * DIM)
#define WIH_OFF ((size_t)NLAY * 3 * HID * DIM)
#define WHH_OFF ((size_t)NLAY * 3 * HID * HID)
#define SROW    40          // smem row stride in bf16

// ---------------- scratch (device globals: allocation-free) ----------------
__device__ float g_h[NLAY * BATCH * HID];
__device__ bf16  g_hd0[2 * BATCH * HID];
__device__ bf16  g_hd1[2 * BATCH * HID];
__device__ bf16  g_xd[2 * (size_t)BATCH * TOUT * DIM];
__device__ bf16  g_xcd[2 * BATCH * DIM];
__device__ bf16  g_wencd[2 * BATCH * HID];
__device__ bf16  g_tmpd[2 * BATCH * DIM];
__device__ float g_logits[BATCH * SIN];
__device__ float g_aw[BATCH * SIN];
__device__ float g_gi[BATCH * 3 * HID];
__device__ float g_gh[BATCH * 3 * HID];
// decomposed weights (hi block, then lo block); attn padded to 128 rows (rest zero)
__device__ bf16 g_attnWd[2 * SINP * (DIM + HID)];
__device__ bf16 g_combWd[2 * DIM * (DIM + HID)];
__device__ bf16 g_Wihd[2 * NLAY * 3 * HID * DIM];
__device__ bf16 g_Whhd[2 * NLAY * 3 * HID * HID];
__device__ bf16 g_out1d[2 * DIM * HID];
__device__ bf16 g_out2d[2 * DIM * DIM];

// ---------------- helpers ----------------
__device__ __forceinline__ void dec2(float v, bf16& hi, bf16& lo) {
    hi = __float2bfloat16(v);
    lo = __float2bfloat16(v - __bfloat162float(hi));
}

__device__ __forceinline__ void mma_bf16(float c[4], const unsigned a[4], const unsigned b0, const unsigned b1) {
    asm volatile(
        "mma.sync.aligned.m16n8k16.row.col.f32.bf16.bf16.f32 "
        "{%0,%1,%2,%3},{%4,%5,%6,%7},{%8,%9},{%0,%1,%2,%3};\n"
        : "+f"(c[0]), "+f"(c[1]), "+f"(c[2]), "+f"(c[3])
        : "r"(a[0]), "r"(a[1]), "r"(a[2]), "r"(a[3]), "r"(b0), "r"(b1));
}

__device__ __forceinline__ void ldsm4(unsigned r[4], unsigned addr) {
    asm volatile("ldmatrix.sync.aligned.m8n8.x4.shared.b16 {%0,%1,%2,%3}, [%4];"
                 : "=r"(r[0]), "=r"(r[1]), "=r"(r[2]), "=r"(r[3]) : "r"(addr));
}

__device__ __forceinline__ void cpa16(unsigned dst, const void* src) {
    asm volatile("cp.async.cg.shared.global [%0], [%1], 16;" :: "r"(dst), "l"(src));
}

// ---------------- gemm argument bundle ----------------
struct GArg {
    const bf16* A0; size_t aoff0; int lda0; int K0;
    const bf16* A1; size_t aoff1; int lda1;
    const bf16* Wd; size_t woff;
    const float* bias;
    float* C; int ldc;
    bf16* Cd; size_t cdoff; int ldcd;
    int N; int K; int act;
};

// ---------------- tensor-core GEMM body ----------------
// BM=64, BN=64, BK=32, 128 threads (4 warps 2x2, warp tile 32x32),
// m16n8k16 bf16 MMA, 3-term hi/lo compensation, cp.async double buffer,
// ldmatrix fragment loads. All loads unguarded (N multiple of 64 padded).
__device__ __forceinline__ void gemm_body(const GArg& g)
{
    __shared__ __align__(16) bf16 As[2][2][64 * SROW];
    __shared__ __align__(16) bf16 Ws[2][2][64 * SROW];

    const int tid = threadIdx.x, lane = tid & 31, warp = tid >> 5;
    const int wm = (warp >> 1) * 32, wn = (warp & 1) * 32;
    const int rowBase = blockIdx.y * 64, colBase = blockIdx.x * 64;

    // per-thread cp.async coords: 2 chunks each for A-hi/A-lo/W-hi/W-lo
    const int r0c = tid >> 2, c0c = (tid & 3) * 8;           // chunk 0
    const int r1c = (tid + 128) >> 2, c1c = c0c;             // chunk 1

    float acc[2][4][4];
#pragma unroll
    for (int mt = 0; mt < 2; mt++)
#pragma unroll
        for (int nt = 0; nt < 4; nt++)
#pragma unroll
            for (int q = 0; q < 4; q++) acc[mt][nt][q] = 0.f;

    const int nsteps = g.K >> 5;

    auto prefetch = [&](int s, int buf) {
        int k0 = s << 5;
        const bf16* Ab; size_t ao; int lda, kk;
        if (k0 < g.K0) { Ab = g.A0; ao = g.aoff0; lda = g.lda0; kk = k0; }
        else           { Ab = g.A1; ao = g.aoff1; lda = g.lda1; kk = k0 - g.K0; }
        {
            const bf16* p0 = Ab + (size_t)(rowBase + r0c) * lda + kk + c0c;
            const bf16* p1 = Ab + (size_t)(rowBase + r1c) * lda + kk + c1c;
            cpa16((unsigned)__cvta_generic_to_shared(&As[buf][0][r0c * SROW + c0c]), p0);
            cpa16((unsigned)__cvta_generic_to_shared(&As[buf][0][r1c * SROW + c1c]), p1);
            cpa16((unsigned)__cvta_generic_to_shared(&As[buf][1][r0c * SROW + c0c]), p0 + ao);
            cpa16((unsigned)__cvta_generic_to_shared(&As[buf][1][r1c * SROW + c1c]), p1 + ao);
        }
        {
            const bf16* p0 = g.Wd + (size_t)(colBase + r0c) * g.K + k0 + c0c;
            const bf16* p1 = g.Wd + (size_t)(colBase + r1c) * g.K + k0 + c1c;
            cpa16((unsigned)__cvta_generic_to_shared(&Ws[buf][0][r0c * SROW + c0c]), p0);
            cpa16((unsigned)__cvta_generic_to_shared(&Ws[buf][0][r1c * SROW + c1c]), p1);
            cpa16((unsigned)__cvta_generic_to_shared(&Ws[buf][1][r0c * SROW + c0c]), p0 + g.woff);
            cpa16((unsigned)__cvta_generic_to_shared(&Ws[buf][1][r1c * SROW + c1c]), p1 + g.woff);
        }
        asm volatile("cp.async.commit_group;");
    };

    prefetch(0, 0);

    // ldmatrix lane coordinates
    const int aRow = lane & 15, aCol = (lane >> 4) << 3;                     // + m0 / + kk16
    const int bRow = ((lane >> 4) << 3) + (lane & 7), bCol = ((lane >> 3) & 1) << 3;

    for (int s = 0; s < nsteps; s++) {
        int buf = s & 1;
        if (s + 1 < nsteps) {
            prefetch(s + 1, buf ^ 1);
            asm volatile("cp.async.wait_group 1;");
        } else {
            asm volatile("cp.async.wait_group 0;");
        }
        __syncthreads();

#pragma unroll
        for (int h = 0; h < 2; h++) {           // two k16 halves of the 32-k slab
            int kk16 = h << 4;
            unsigned ah[2][4], al[2][4], bh[2][4], bl[2][4];
#pragma unroll
            for (int mt = 0; mt < 2; mt++) {
                int ro = (wm + mt * 16 + aRow) * SROW + kk16 + aCol;
                ldsm4(ah[mt], (unsigned)__cvta_generic_to_shared(&As[buf][0][ro]));
                ldsm4(al[mt], (unsigned)__cvta_generic_to_shared(&As[buf][1][ro]));
            }
#pragma unroll
            for (int np = 0; np < 2; np++) {
                int ro = (wn + np * 16 + bRow) * SROW + kk16 + bCol;
                ldsm4(bh[np], (unsigned)__cvta_generic_to_shared(&Ws[buf][0][ro]));
                ldsm4(bl[np], (unsigned)__cvta_generic_to_shared(&Ws[buf][1][ro]));
            }
#pragma unroll
            for (int mt = 0; mt < 2; mt++)
#pragma unroll
                for (int nt = 0; nt < 4; nt++) {
                    int np = nt >> 1, q = (nt & 1) * 2;
                    mma_bf16(acc[mt][nt], ah[mt], bh[np][q], bh[np][q + 1]);
                    mma_bf16(acc[mt][nt], ah[mt], bl[np][q], bl[np][q + 1]);
                    mma_bf16(acc[mt][nt], al[mt], bh[np][q], bh[np][q + 1]);
                }
        }
        __syncthreads();
    }

    // epilogue
#pragma unroll
    for (int mt = 0; mt < 2; mt++)
#pragma unroll
        for (int nt = 0; nt < 4; nt++) {
            int r0 = rowBase + wm + mt * 16 + (lane >> 2);
            int c0 = colBase + wn + nt * 8 + (lane & 3) * 2;
            if (c0 >= g.N) continue;
            float b0 = g.bias ? g.bias[c0] : 0.f;
            float b1 = g.bias ? g.bias[c0 + 1] : 0.f;
#pragma unroll
            for (int p = 0; p < 2; p++) {
                int r = r0 + p * 8;
                float v0 = acc[mt][nt][p * 2] + b0;
                float v1 = acc[mt][nt][p * 2 + 1] + b1;
                if (g.act == 1) { v0 = fmaxf(v0, 0.f); v1 = fmaxf(v1, 0.f); }
                if (g.C) {
                    g.C[(size_t)r * g.ldc + c0] = v0;
                    g.C[(size_t)r * g.ldc + c0 + 1] = v1;
                }
                if (g.Cd) {
                    bf16 h0, l0, h1, l1;
                    dec2(v0, h0, l0);
                    dec2(v1, h1, l1);
                    size_t o = (size_t)r * g.ldcd + c0;
                    g.Cd[o] = h0; g.Cd[o + 1] = h1;
                    g.Cd[g.cdoff + o] = l0; g.Cd[g.cdoff + o + 1] = l1;
                }
            }
        }
}

__global__ __launch_bounds__(128) void gemm_tc(GArg g)          { gemm_body(g); }
__global__ __launch_bounds__(128) void gemm_tc2(GArg a, GArg b) { gemm_body(blockIdx.z ? b : a); }

// ---------------- weight / input decomposition ----------------
__global__ void decomp_kernel(const float* __restrict__ src, bf16* __restrict__ dst,
                              size_t off, int n)
{
    int i = blockIdx.x * 256 + threadIdx.x;
    if (i < n) {
        bf16 hi, lo;
        dec2(src[i], hi, lo);
        dst[i] = hi;
        dst[off + i] = lo;
    }
}

__global__ void init_h_kernel(const float* __restrict__ hidden,
                              float* __restrict__ h,
                              bf16* __restrict__ hd0, bf16* __restrict__ hd1)
{
    int i = blockIdx.x * 256 + threadIdx.x;
    float v = hidden[i];
    h[i] = v;
    int l = i >> 18;
    int j = i & (BH - 1);
    bf16* hd = l ? hd1 : hd0;
    bf16 hi, lo;
    dec2(v, hi, lo);
    hd[j] = hi;
    hd[BH + j] = lo;
}

__global__ void copy_kernel(const float* __restrict__ src, float* __restrict__ dst, int n)
{
    int i = blockIdx.x * 256 + threadIdx.x;
    if (i < n) dst[i] = src[i];
}

// ---------------- softmax over S_IN=96 ----------------
__global__ void softmax_kernel(const float* __restrict__ logits,
                               float* __restrict__ aw,
                               float* __restrict__ out_attn, int t)
{
    __shared__ float sm[128];
    int b = blockIdx.x, tid = threadIdx.x;
    float v = (tid < SIN) ? logits[b * SIN + tid] : -1e30f;
    sm[tid] = v; __syncthreads();
    for (int s = 64; s > 0; s >>= 1) {
        if (tid < s) sm[tid] = fmaxf(sm[tid], sm[tid + s]);
        __syncthreads();
    }
    float mx = sm[0]; __syncthreads();
    float e = (tid < SIN) ? expf(v - mx) : 0.f;
    sm[tid] = e; __syncthreads();
    for (int s = 64; s > 0; s >>= 1) {
        if (tid < s) sm[tid] += sm[tid + s];
        __syncthreads();
    }
    float inv = 1.f / sm[0];
    if (tid < SIN) {
        float a = e * inv;
        aw[b * SIN + tid] = a;
        out_attn[(size_t)b * TOUT * SIN + (size_t)t * SIN + tid] = a;
    }
}

// ---------------- w_enc ----------------
__global__ void wenc_kernel(const float* __restrict__ aw,
                            const float* __restrict__ enc,
                            bf16* __restrict__ wencd)
{
    __shared__ float a[SIN];
    int b = blockIdx.y;
    int h = blockIdx.x * 256 + threadIdx.x;
    if (threadIdx.x < SIN) a[threadIdx.x] = aw[b * SIN + threadIdx.x];
    __syncthreads();
    const float* e = enc + (size_t)b * SIN * HID + h;
    float acc = 0.f;
#pragma unroll 8
    for (int s = 0; s < SIN; s++) acc = fmaf(a[s], e[(size_t)s * HID], acc);
    bf16 hi, lo;
    dec2(acc, hi, lo);
    int idx = b * HID + h;
    wencd[idx] = hi;
    wencd[BH + idx] = lo;
}

// ---------------- GRU gate combine ----------------
__global__ void gate_kernel(const float* __restrict__ gi,
                            const float* __restrict__ gh,
                            float* __restrict__ h,
                            bf16* __restrict__ hd)
{
    int idx = blockIdx.x * 256 + threadIdx.x;
    int b = idx >> 10;
    int j = idx & 1023;
    const float* gib = gi + (size_t)b * 3 * HID;
    const float* ghb = gh + (size_t)b * 3 * HID;
    float ir = gib[j], iz = gib[HID + j], in_ = gib[2 * HID + j];
    float hr = ghb[j], hz = ghb[HID + j], hn  = ghb[2 * HID + j];
    float r = 1.f / (1.f + expf(-(ir + hr)));
    float z = 1.f / (1.f + expf(-(iz + hz)));
    float n = tanhf(in_ + r * hn);
    float ho = h[idx];
    float v = (1.f - z) * n + z * ho;
    h[idx] = v;
    bf16 hi, lo;
    dec2(v, hi, lo);
    hd[idx] = hi;
    hd[BH + idx] = lo;
}

// ---------------- host orchestration ----------------
extern "C" void kernel_launch(void* const* d_in, const int* in_sizes, int n_in,
                              void* d_out, int out_size)
{
    const float* target = (const float*)d_in[0];
    const float* hidden = (const float*)d_in[1];
    const float* enc    = (const float*)d_in[2];
    const float* attn_W = (const float*)d_in[3];
    const float* attn_b = (const float*)d_in[4];
    const float* comb_W = (const float*)d_in[5];
    const float* comb_b = (const float*)d_in[6];
    const float* W_ih   = (const float*)d_in[7];
    const float* W_hh   = (const float*)d_in[8];
    const float* b_ih   = (const float*)d_in[9];
    const float* b_hh   = (const float*)d_in[10];
    const float* out1_W = (const float*)d_in[11];
    const float* out1_b = (const float*)d_in[12];
    const float* out2_W = (const float*)d_in[13];
    const float* out2_b = (const float*)d_in[14];

    float* out   = (float*)d_out;
    float* out_y = out;
    float* out_h = out + (size_t)BATCH * TOUT * DIM;
    float* out_a = out_h + (size_t)NLAY * BATCH * HID;

    float *h_, *logits, *aw, *gi, *gh;
    bf16 *hd0, *hd1, *xd, *xcd, *wencd, *tmpd;
    bf16 *attnWd, *combWd, *Wihd, *Whhd, *out1d, *out2d;
    cudaGetSymbolAddress((void**)&h_,     g_h);
    cudaGetSymbolAddress((void**)&hd0,    g_hd0);
    cudaGetSymbolAddress((void**)&hd1,    g_hd1);
    cudaGetSymbolAddress((void**)&xd,     g_xd);
    cudaGetSymbolAddress((void**)&xcd,    g_xcd);
    cudaGetSymbolAddress((void**)&wencd,  g_wencd);
    cudaGetSymbolAddress((void**)&tmpd,   g_tmpd);
    cudaGetSymbolAddress((void**)&logits, g_logits);
    cudaGetSymbolAddress((void**)&aw,     g_aw);
    cudaGetSymbolAddress((void**)&gi,     g_gi);
    cudaGetSymbolAddress((void**)&gh,     g_gh);
    cudaGetSymbolAddress((void**)&attnWd, g_attnWd);
    cudaGetSymbolAddress((void**)&combWd, g_combWd);
    cudaGetSymbolAddress((void**)&Wihd,   g_Wihd);
    cudaGetSymbolAddress((void**)&Whhd,   g_Whhd);
    cudaGetSymbolAddress((void**)&out1d,  g_out1d);
    cudaGetSymbolAddress((void**)&out2d,  g_out2d);

    // prologue: decompose weights + target, init hidden
    {
        int n;
        n = SIN * (DIM + HID);   // attn: padded hi/lo offset, rows 96..127 stay zero
        decomp_kernel<<<(n + 255) / 256, 256>>>(attn_W, attnWd, (size_t)SINP * (DIM + HID), n);
        n = DIM * (DIM + HID);
        decomp_kernel<<<(n + 255) / 256, 256>>>(comb_W, combWd, n, n);
        n = NLAY * 3 * HID * DIM;
        decomp_kernel<<<(n + 255) / 256, 256>>>(W_ih, Wihd, n, n);
        n = NLAY * 3 * HID * HID;
        decomp_kernel<<<(n + 255) / 256, 256>>>(W_hh, Whhd, n, n);
        n = DIM * HID;
        decomp_kernel<<<(n + 255) / 256, 256>>>(out1_W, out1d, n, n);
        n = DIM * DIM;
        decomp_kernel<<<(n + 255) / 256, 256>>>(out2_W, out2d, n, n);
        n = (int)(BATCH * TOUT * DIM);
        decomp_kernel<<<(n + 255) / 256, 256>>>(target, xd, XOFF, n);
        init_h_kernel<<<(NLAY * BH) / 256, 256>>>(hidden, h_, hd0, hd1);
    }

    const int LDX = TOUT * DIM;
    const size_t BD = (size_t)BATCH * DIM;

    for (int t = 0; t < TOUT; t++) {
        const bf16* xt = xd + (size_t)t * DIM;

        // attn logits (256 x 96, K=2048, weights padded to N=128)
        GArg ga = { xt, XOFF, LDX, DIM, hd1, BH, HID,
                    attnWd, (size_t)SINP * (DIM + HID), attn_b,
                    logits, SIN, nullptr, 0, 0, SIN, DIM + HID, 0 };
        gemm_tc<<<dim3(2, 4), 128>>>(ga);
        softmax_kernel<<<BATCH, 128>>>(logits, aw, out_a, t);
        wenc_kernel<<<dim3(HID / 256, BATCH), 256>>>(aw, enc, wencd);

        // xc = relu(cat(x, w_enc) @ comb_W^T + b) -> decomposed
        GArg gc = { xt, XOFF, LDX, DIM, wencd, BH, HID,
                    combWd, (size_t)DIM * (DIM + HID), comb_b,
                    nullptr, 0, xcd, BD, DIM, DIM, DIM + HID, 1 };
        gemm_tc<<<dim3(16, 4), 128>>>(gc);

        // GRU layer 0: gi and gh fused in one launch (blockIdx.z)
        GArg gi0 = { xcd, BD, DIM, DIM, nullptr, 0, 0,
                     Wihd, WIH_OFF, b_ih, gi, 3 * HID,
                     nullptr, 0, 0, 3 * HID, DIM, 0 };
        GArg gh0 = { hd0, BH, HID, HID, nullptr, 0, 0,
                     Whhd, WHH_OFF, b_hh, gh, 3 * HID,
                     nullptr, 0, 0, 3 * HID, HID, 0 };
        gemm_tc2<<<dim3(48, 4, 2), 128>>>(gi0, gh0);
        gate_kernel<<<BH / 256, 256>>>(gi, gh, h_, hd0);

        // GRU layer 1
        GArg gi1 = { hd0, BH, HID, HID, nullptr, 0, 0,
                     Wihd + (size_t)3 * HID * DIM, WIH_OFF, b_ih + 3 * HID,
                     gi, 3 * HID, nullptr, 0, 0, 3 * HID, HID, 0 };
        GArg gh1 = { hd1, BH, HID, HID, nullptr, 0, 0,
                     Whhd + (size_t)3 * HID * HID, WHH_OFF, b_hh + 3 * HID,
                     gh, 3 * HID, nullptr, 0, 0, 3 * HID, HID, 0 };
        gemm_tc2<<<dim3(48, 4, 2), 128>>>(gi1, gh1);
        gate_kernel<<<BH / 256, 256>>>(gi, gh, h_ + BH, hd1);

        // output head
        GArg go1 = { hd1, BH, HID, HID, nullptr, 0, 0,
                     out1d, (size_t)DIM * HID, out1_b,
                     nullptr, 0, tmpd, BD, DIM, DIM, HID, 0 };
        gemm_tc<<<dim3(16, 4), 128>>>(go1);
        GArg go2 = { tmpd, BD, DIM, DIM, nullptr, 0, 0,
                     out2d, (size_t)DIM * DIM, out2_b,
                     out_y + (size_t)t * DIM, LDX, nullptr, 0, 0, DIM, DIM, 0 };
        gemm_tc<<<dim3(16, 4), 128>>>(go2);
    }

    copy_kernel<<<(NLAY * BH) / 256, 256>>>(h_, out_h, NLAY * BH);
}

// round 8
// speedup vs baseline: 3.6792x; 1.1400x over previous
#include <cuda_runtime.h>
#include <cuda_bf16.h>
#include <math.h>

#define BATCH 256
#define TOUT  36
#define SIN   96
#define SINP  128
#define DIM   1024
#define HID   1024
#define NLAY  2

typedef __nv_bfloat16 bf16;

#define BH      (BATCH * HID)
#define PAR     (2 * BH)             // parity stride for hd1 double buffer
#define XOFF    ((size_t)BATCH * TOUT * DIM)
#define WIH_OFF ((size_t)NLAY * 3 * HID * DIM)
#define WHH_OFF ((size_t)NLAY * 3 * HID * HID)
#define SROW    40

// ---------------- scratch ----------------
__device__ float g_h[NLAY * BATCH * HID];
__device__ bf16  g_hd0[2 * BATCH * HID];
__device__ bf16  g_hd1[2][2 * BATCH * HID];      // parity double buffer
__device__ bf16  g_xd[2 * (size_t)BATCH * TOUT * DIM];
__device__ bf16  g_xcd[2 * BATCH * DIM];
__device__ bf16  g_wencd[2 * BATCH * HID];
__device__ bf16  g_tmpd[2 * BATCH * DIM];
__device__ float g_logits[BATCH * SIN];
__device__ float g_aw[BATCH * SIN];
__device__ float g_gi[BATCH * 3 * HID];
__device__ float g_gh0[BATCH * 3 * HID];
__device__ float g_gh1[BATCH * 3 * HID];
__device__ bf16 g_attnWd[2 * SINP * (DIM + HID)];
__device__ bf16 g_combWd[2 * DIM * (DIM + HID)];
__device__ bf16 g_Wihd[2 * NLAY * 3 * HID * DIM];
__device__ bf16 g_Whhd[2 * NLAY * 3 * HID * HID];
__device__ bf16 g_out1d[2 * DIM * HID];
__device__ bf16 g_out2d[2 * DIM * DIM];

// ---------------- helpers ----------------
__device__ __forceinline__ void dec2(float v, bf16& hi, bf16& lo) {
    hi = __float2bfloat16(v);
    lo = __float2bfloat16(v - __bfloat162float(hi));
}

__device__ __forceinline__ void mma_bf16(float c[4], const unsigned a[4], const unsigned b0, const unsigned b1) {
    asm volatile(
        "mma.sync.aligned.m16n8k16.row.col.f32.bf16.bf16.f32 "
        "{%0,%1,%2,%3},{%4,%5,%6,%7},{%8,%9},{%0,%1,%2,%3};\n"
        : "+f"(c[0]), "+f"(c[1]), "+f"(c[2]), "+f"(c[3])
        : "r"(a[0]), "r"(a[1]), "r"(a[2]), "r"(a[3]), "r"(b0), "r"(b1));
}

__device__ __forceinline__ void ldsm4(unsigned r[4], unsigned addr) {
    asm volatile("ldmatrix.sync.aligned.m8n8.x4.shared.b16 {%0,%1,%2,%3}, [%4];"
                 : "=r"(r[0]), "=r"(r[1]), "=r"(r[2]), "=r"(r[3]) : "r"(addr));
}

__device__ __forceinline__ void cpa16(unsigned dst, const void* src) {
    asm volatile("cp.async.cg.shared.global [%0], [%1], 16;" :: "r"(dst), "l"(src));
}

// ---------------- gemm argument bundle ----------------
struct GArg {
    const bf16* A0; size_t aoff0; int lda0; int K0;
    const bf16* A1; size_t aoff1; int lda1;
    const bf16* Wd; size_t woff;
    const float* bias;
    float* C; int ldc;
    bf16* Cd; size_t cdoff; int ldcd;
    int N; int K; int act;
};

// ---------------- tensor-core GEMM body (BM=64,BN=64,BK=32, 4 warps) ------
__device__ __forceinline__ void gemm_body(const GArg& g)
{
    __shared__ __align__(16) bf16 As[2][2][64 * SROW];
    __shared__ __align__(16) bf16 Ws[2][2][64 * SROW];

    const int tid = threadIdx.x, lane = tid & 31, warp = tid >> 5;
    const int wm = (warp >> 1) * 32, wn = (warp & 1) * 32;
    const int rowBase = blockIdx.y * 64, colBase = blockIdx.x * 64;

    const int r0c = tid >> 2, c0c = (tid & 3) * 8;
    const int r1c = (tid + 128) >> 2, c1c = c0c;

    float acc[2][4][4];
#pragma unroll
    for (int mt = 0; mt < 2; mt++)
#pragma unroll
        for (int nt = 0; nt < 4; nt++)
#pragma unroll
            for (int q = 0; q < 4; q++) acc[mt][nt][q] = 0.f;

    const int nsteps = g.K >> 5;

    auto prefetch = [&](int s, int buf) {
        int k0 = s << 5;
        const bf16* Ab; size_t ao; int lda, kk;
        if (k0 < g.K0) { Ab = g.A0; ao = g.aoff0; lda = g.lda0; kk = k0; }
        else           { Ab = g.A1; ao = g.aoff1; lda = g.lda1; kk = k0 - g.K0; }
        {
            const bf16* p0 = Ab + (size_t)(rowBase + r0c) * lda + kk + c0c;
            const bf16* p1 = Ab + (size_t)(rowBase + r1c) * lda + kk + c1c;
            cpa16((unsigned)__cvta_generic_to_shared(&As[buf][0][r0c * SROW + c0c]), p0);
            cpa16((unsigned)__cvta_generic_to_shared(&As[buf][0][r1c * SROW + c1c]), p1);
            cpa16((unsigned)__cvta_generic_to_shared(&As[buf][1][r0c * SROW + c0c]), p0 + ao);
            cpa16((unsigned)__cvta_generic_to_shared(&As[buf][1][r1c * SROW + c1c]), p1 + ao);
        }
        {
            const bf16* p0 = g.Wd + (size_t)(colBase + r0c) * g.K + k0 + c0c;
            const bf16* p1 = g.Wd + (size_t)(colBase + r1c) * g.K + k0 + c1c;
            cpa16((unsigned)__cvta_generic_to_shared(&Ws[buf][0][r0c * SROW + c0c]), p0);
            cpa16((unsigned)__cvta_generic_to_shared(&Ws[buf][0][r1c * SROW + c1c]), p1);
            cpa16((unsigned)__cvta_generic_to_shared(&Ws[buf][1][r0c * SROW + c0c]), p0 + g.woff);
            cpa16((unsigned)__cvta_generic_to_shared(&Ws[buf][1][r1c * SROW + c1c]), p1 + g.woff);
        }
        asm volatile("cp.async.commit_group;");
    };

    prefetch(0, 0);

    const int aRow = lane & 15, aCol = (lane >> 4) << 3;
    const int bRow = ((lane >> 4) << 3) + (lane & 7), bCol = ((lane >> 3) & 1) << 3;

    for (int s = 0; s < nsteps; s++) {
        int buf = s & 1;
        if (s + 1 < nsteps) {
            prefetch(s + 1, buf ^ 1);
            asm volatile("cp.async.wait_group 1;");
        } else {
            asm volatile("cp.async.wait_group 0;");
        }
        __syncthreads();

#pragma unroll
        for (int h = 0; h < 2; h++) {
            int kk16 = h << 4;
            unsigned ah[2][4], al[2][4], bh[2][4], bl[2][4];
#pragma unroll
            for (int mt = 0; mt < 2; mt++) {
                int ro = (wm + mt * 16 + aRow) * SROW + kk16 + aCol;
                ldsm4(ah[mt], (unsigned)__cvta_generic_to_shared(&As[buf][0][ro]));
                ldsm4(al[mt], (unsigned)__cvta_generic_to_shared(&As[buf][1][ro]));
            }
#pragma unroll
            for (int np = 0; np < 2; np++) {
                int ro = (wn + np * 16 + bRow) * SROW + kk16 + bCol;
                ldsm4(bh[np], (unsigned)__cvta_generic_to_shared(&Ws[buf][0][ro]));
                ldsm4(bl[np], (unsigned)__cvta_generic_to_shared(&Ws[buf][1][ro]));
            }
#pragma unroll
            for (int mt = 0; mt < 2; mt++)
#pragma unroll
                for (int nt = 0; nt < 4; nt++) {
                    int np = nt >> 1, q = (nt & 1) * 2;
                    mma_bf16(acc[mt][nt], ah[mt], bh[np][q], bh[np][q + 1]);
                    mma_bf16(acc[mt][nt], ah[mt], bl[np][q], bl[np][q + 1]);
                    mma_bf16(acc[mt][nt], al[mt], bh[np][q], bh[np][q + 1]);
                }
        }
        __syncthreads();
    }

#pragma unroll
    for (int mt = 0; mt < 2; mt++)
#pragma unroll
        for (int nt = 0; nt < 4; nt++) {
            int r0 = rowBase + wm + mt * 16 + (lane >> 2);
            int c0 = colBase + wn + nt * 8 + (lane & 3) * 2;
            if (c0 >= g.N) continue;
            float b0 = g.bias ? g.bias[c0] : 0.f;
            float b1 = g.bias ? g.bias[c0 + 1] : 0.f;
#pragma unroll
            for (int p = 0; p < 2; p++) {
                int r = r0 + p * 8;
                float v0 = acc[mt][nt][p * 2] + b0;
                float v1 = acc[mt][nt][p * 2 + 1] + b1;
                if (g.act == 1) { v0 = fmaxf(v0, 0.f); v1 = fmaxf(v1, 0.f); }
                if (g.C) {
                    g.C[(size_t)r * g.ldc + c0] = v0;
                    g.C[(size_t)r * g.ldc + c0 + 1] = v1;
                }
                if (g.Cd) {
                    bf16 h0, l0, h1, l1;
                    dec2(v0, h0, l0);
                    dec2(v1, h1, l1);
                    size_t o = (size_t)r * g.ldcd + c0;
                    g.Cd[o] = h0; g.Cd[o + 1] = h1;
                    g.Cd[g.cdoff + o] = l0; g.Cd[g.cdoff + o + 1] = l1;
                }
            }
        }
}

__global__ __launch_bounds__(128) void gemm_tc(GArg g)          { gemm_body(g); }
__global__ __launch_bounds__(128) void gemm_tc2(GArg a, GArg b) { gemm_body(blockIdx.z ? b : a); }

// ---------------- decomposition / init ----------------
__global__ void decomp_kernel(const float* __restrict__ src, bf16* __restrict__ dst,
                              size_t off, int n)
{
    int i = blockIdx.x * 256 + threadIdx.x;
    if (i < n) {
        bf16 hi, lo;
        dec2(src[i], hi, lo);
        dst[i] = hi;
        dst[off + i] = lo;
    }
}

__global__ void init_h_kernel(const float* __restrict__ hidden,
                              float* __restrict__ h,
                              bf16* __restrict__ hd0, bf16* __restrict__ hd1init)
{
    int i = blockIdx.x * 256 + threadIdx.x;
    float v = hidden[i];
    h[i] = v;
    int l = i >> 18;
    int j = i & (BH - 1);
    bf16* hd = l ? hd1init : hd0;
    bf16 hi, lo;
    dec2(v, hi, lo);
    hd[j] = hi;
    hd[BH + j] = lo;
}

__global__ void copy_kernel(const float* __restrict__ src, float* __restrict__ dst, int n)
{
    int i = blockIdx.x * 256 + threadIdx.x;
    if (i < n) dst[i] = src[i];
}

// ---------------- softmax ----------------
__global__ void softmax_kernel(const float* __restrict__ logits,
                               float* __restrict__ aw,
                               float* __restrict__ out_attn, int t)
{
    __shared__ float sm[128];
    int b = blockIdx.x, tid = threadIdx.x;
    float v = (tid < SIN) ? logits[b * SIN + tid] : -1e30f;
    sm[tid] = v; __syncthreads();
    for (int s = 64; s > 0; s >>= 1) {
        if (tid < s) sm[tid] = fmaxf(sm[tid], sm[tid + s]);
        __syncthreads();
    }
    float mx = sm[0]; __syncthreads();
    float e = (tid < SIN) ? expf(v - mx) : 0.f;
    sm[tid] = e; __syncthreads();
    for (int s = 64; s > 0; s >>= 1) {
        if (tid < s) sm[tid] += sm[tid + s];
        __syncthreads();
    }
    float inv = 1.f / sm[0];
    if (tid < SIN) {
        float a = e * inv;
        aw[b * SIN + tid] = a;
        out_attn[(size_t)b * TOUT * SIN + (size_t)t * SIN + tid] = a;
    }
}

// ---------------- w_enc (float4, 4 elems/thread) ----------------
__global__ void wenc_kernel(const float* __restrict__ aw,
                            const float* __restrict__ enc,
                            bf16* __restrict__ wencd)
{
    __shared__ float a[SIN];
    int b = blockIdx.x;
    int h4 = threadIdx.x;                 // 256 threads * 4 = 1024
    if (threadIdx.x < SIN) a[threadIdx.x] = aw[b * SIN + threadIdx.x];
    __syncthreads();
    const float4* e = reinterpret_cast<const float4*>(enc + (size_t)b * SIN * HID) + h4;
    float ax = 0.f, ay = 0.f, az = 0.f, aww = 0.f;
#pragma unroll 4
    for (int s = 0; s < SIN; s++) {
        float4 v = e[(size_t)s * (HID / 4)];
        float w = a[s];
        ax = fmaf(w, v.x, ax); ay = fmaf(w, v.y, ay);
        az = fmaf(w, v.z, az); aww = fmaf(w, v.w, aww);
    }
    int idx = b * HID + h4 * 4;
    float r4[4] = {ax, ay, az, aww};
#pragma unroll
    for (int q = 0; q < 4; q++) {
        bf16 hi, lo;
        dec2(r4[q], hi, lo);
        wencd[idx + q] = hi;
        wencd[BH + idx + q] = lo;
    }
}

// ---------------- GRU gate combine ----------------
__global__ void gate_kernel(const float* __restrict__ gi,
                            const float* __restrict__ gh,
                            float* __restrict__ h,
                            bf16* __restrict__ hd)
{
    int idx = blockIdx.x * 256 + threadIdx.x;
    int b = idx >> 10;
    int j = idx & 1023;
    const float* gib = gi + (size_t)b * 3 * HID;
    const float* ghb = gh + (size_t)b * 3 * HID;
    float ir = gib[j], iz = gib[HID + j], in_ = gib[2 * HID + j];
    float hr = ghb[j], hz = ghb[HID + j], hn  = ghb[2 * HID + j];
    float r = 1.f / (1.f + expf(-(ir + hr)));
    float z = 1.f / (1.f + expf(-(iz + hz)));
    float n = tanhf(in_ + r * hn);
    float ho = h[idx];
    float v = (1.f - z) * n + z * ho;
    h[idx] = v;
    bf16 hi, lo;
    dec2(v, hi, lo);
    hd[idx] = hi;
    hd[BH + idx] = lo;
}

// ---------------- host orchestration ----------------
extern "C" void kernel_launch(void* const* d_in, const int* in_sizes, int n_in,
                              void* d_out, int out_size)
{
    const float* target = (const float*)d_in[0];
    const float* hidden = (const float*)d_in[1];
    const float* enc    = (const float*)d_in[2];
    const float* attn_W = (const float*)d_in[3];
    const float* attn_b = (const float*)d_in[4];
    const float* comb_W = (const float*)d_in[5];
    const float* comb_b = (const float*)d_in[6];
    const float* W_ih   = (const float*)d_in[7];
    const float* W_hh   = (const float*)d_in[8];
    const float* b_ih   = (const float*)d_in[9];
    const float* b_hh   = (const float*)d_in[10];
    const float* out1_W = (const float*)d_in[11];
    const float* out1_b = (const float*)d_in[12];
    const float* out2_W = (const float*)d_in[13];
    const float* out2_b = (const float*)d_in[14];

    float* out   = (float*)d_out;
    float* out_y = out;
    float* out_h = out + (size_t)BATCH * TOUT * DIM;
    float* out_a = out_h + (size_t)NLAY * BATCH * HID;

    float *h_, *logits, *aw, *gi, *gh0b, *gh1b;
    bf16 *hd0, *hd1, *xd, *xcd, *wencd, *tmpd;
    bf16 *attnWd, *combWd, *Wihd, *Whhd, *out1d, *out2d;
    cudaGetSymbolAddress((void**)&h_,     g_h);
    cudaGetSymbolAddress((void**)&hd0,    g_hd0);
    cudaGetSymbolAddress((void**)&hd1,    g_hd1);
    cudaGetSymbolAddress((void**)&xd,     g_xd);
    cudaGetSymbolAddress((void**)&xcd,    g_xcd);
    cudaGetSymbolAddress((void**)&wencd,  g_wencd);
    cudaGetSymbolAddress((void**)&tmpd,   g_tmpd);
    cudaGetSymbolAddress((void**)&logits, g_logits);
    cudaGetSymbolAddress((void**)&aw,     g_aw);
    cudaGetSymbolAddress((void**)&gi,     g_gi);
    cudaGetSymbolAddress((void**)&gh0b,   g_gh0);
    cudaGetSymbolAddress((void**)&gh1b,   g_gh1);
    cudaGetSymbolAddress((void**)&attnWd, g_attnWd);
    cudaGetSymbolAddress((void**)&combWd, g_combWd);
    cudaGetSymbolAddress((void**)&Wihd,   g_Wihd);
    cudaGetSymbolAddress((void**)&Whhd,   g_Whhd);
    cudaGetSymbolAddress((void**)&out1d,  g_out1d);
    cudaGetSymbolAddress((void**)&out2d,  g_out2d);

    // one-time streams/events (created on the first, non-captured call)
    static cudaStream_t s2 = nullptr;
    static cudaEvent_t e_g1 = nullptr, e_gh = nullptr, e_done = nullptr;
    if (!s2) {
        cudaStreamCreateWithFlags(&s2, cudaStreamNonBlocking);
        cudaEventCreateWithFlags(&e_g1,   cudaEventDisableTiming);
        cudaEventCreateWithFlags(&e_gh,   cudaEventDisableTiming);
        cudaEventCreateWithFlags(&e_done, cudaEventDisableTiming);
    }

    // prologue (default stream)
    {
        int n;
        n = SIN * (DIM + HID);
        decomp_kernel<<<(n + 255) / 256, 256>>>(attn_W, attnWd, (size_t)SINP * (DIM + HID), n);
        n = DIM * (DIM + HID);
        decomp_kernel<<<(n + 255) / 256, 256>>>(comb_W, combWd, n, n);
        n = NLAY * 3 * HID * DIM;
        decomp_kernel<<<(n + 255) / 256, 256>>>(W_ih, Wihd, n, n);
        n = NLAY * 3 * HID * HID;
        decomp_kernel<<<(n + 255) / 256, 256>>>(W_hh, Whhd, n, n);
        n = DIM * HID;
        decomp_kernel<<<(n + 255) / 256, 256>>>(out1_W, out1d, n, n);
        n = DIM * DIM;
        decomp_kernel<<<(n + 255) / 256, 256>>>(out2_W, out2d, n, n);
        n = (int)(BATCH * TOUT * DIM);
        decomp_kernel<<<(n + 255) / 256, 256>>>(target, xd, XOFF, n);
        // h1(−1) readers use parity buffer 1
        init_h_kernel<<<(NLAY * BH) / 256, 256>>>(hidden, h_, hd0, hd1 + PAR);
    }
    cudaEventRecord(e_g1, 0);

    const int LDX = TOUT * DIM;
    const size_t BD = (size_t)BATCH * DIM;

    for (int t = 0; t < TOUT; t++) {
        bf16* hd1_rd = hd1 + ((t - 1) & 1) * (size_t)PAR;   // h1(t-1)
        bf16* hd1_wr = hd1 + (t & 1) * (size_t)PAR;         // h1(t)
        const bf16* xt = xd + (size_t)t * DIM;

        // ---- stream2: gh pair for step t, then out-head for step t-1 ----
        cudaStreamWaitEvent(s2, e_g1, 0);
        GArg gh0a = { hd0, BH, HID, HID, nullptr, 0, 0,
                      Whhd, WHH_OFF, b_hh, gh0b, 3 * HID,
                      nullptr, 0, 0, 3 * HID, HID, 0 };
        GArg gh1a = { hd1_rd, BH, HID, HID, nullptr, 0, 0,
                      Whhd + (size_t)3 * HID * HID, WHH_OFF, b_hh + 3 * HID,
                      gh1b, 3 * HID, nullptr, 0, 0, 3 * HID, HID, 0 };
        gemm_tc2<<<dim3(48, 4, 2), 128, 0, s2>>>(gh0a, gh1a);
        cudaEventRecord(e_gh, s2);
        if (t > 0) {
            bf16* hprev = hd1 + ((t - 1) & 1) * (size_t)PAR;
            GArg go1 = { hprev, BH, HID, HID, nullptr, 0, 0,
                         out1d, (size_t)DIM * HID, out1_b,
                         nullptr, 0, tmpd, BD, DIM, DIM, HID, 0 };
            gemm_tc<<<dim3(16, 4), 128, 0, s2>>>(go1);
            GArg go2 = { tmpd, BD, DIM, DIM, nullptr, 0, 0,
                         out2d, (size_t)DIM * DIM, out2_b,
                         out_y + (size_t)(t - 1) * DIM, LDX,
                         nullptr, 0, 0, DIM, DIM, 0 };
            gemm_tc<<<dim3(16, 4), 128, 0, s2>>>(go2);
        }

        // ---- stream1 (default): attention chain + gi + gates ----
        GArg ga = { xt, XOFF, LDX, DIM, hd1_rd, BH, HID,
                    attnWd, (size_t)SINP * (DIM + HID), attn_b,
                    logits, SIN, nullptr, 0, 0, SIN, DIM + HID, 0 };
        gemm_tc<<<dim3(2, 4), 128>>>(ga);
        softmax_kernel<<<BATCH, 128>>>(logits, aw, out_a, t);
        wenc_kernel<<<BATCH, 256>>>(aw, enc, wencd);

        GArg gc = { xt, XOFF, LDX, DIM, wencd, BH, HID,
                    combWd, (size_t)DIM * (DIM + HID), comb_b,
                    nullptr, 0, xcd, BD, DIM, DIM, DIM + HID, 1 };
        gemm_tc<<<dim3(16, 4), 128>>>(gc);

        GArg gi0 = { xcd, BD, DIM, DIM, nullptr, 0, 0,
                     Wihd, WIH_OFF, b_ih, gi, 3 * HID,
                     nullptr, 0, 0, 3 * HID, DIM, 0 };
        gemm_tc<<<dim3(48, 4), 128>>>(gi0);

        cudaStreamWaitEvent(0, e_gh, 0);
        gate_kernel<<<BH / 256, 256>>>(gi, gh0b, h_, hd0);

        GArg gi1 = { hd0, BH, HID, HID, nullptr, 0, 0,
                     Wihd + (size_t)3 * HID * DIM, WIH_OFF, b_ih + 3 * HID,
                     gi, 3 * HID, nullptr, 0, 0, 3 * HID, HID, 0 };
        gemm_tc<<<dim3(48, 4), 128>>>(gi1);
        gate_kernel<<<BH / 256, 256>>>(gi, gh1b, h_ + BH, hd1_wr);
        cudaEventRecord(e_g1, 0);
    }

    // tail: out-head for t=35 on stream2, then join + final hidden copy
    cudaStreamWaitEvent(s2, e_g1, 0);
    {
        bf16* hlast = hd1 + ((TOUT - 1) & 1) * (size_t)PAR;
        GArg go1 = { hlast, BH, HID, HID, nullptr, 0, 0,
                     out1d, (size_t)DIM * HID, out1_b,
                     nullptr, 0, tmpd, BD, DIM, DIM, HID, 0 };
        gemm_tc<<<dim3(16, 4), 128, 0, s2>>>(go1);
        GArg go2 = { tmpd, BD, DIM, DIM, nullptr, 0, 0,
                     out2d, (size_t)DIM * DIM, out2_b,
                     out_y + (size_t)(TOUT - 1) * DIM, LDX,
                     nullptr, 0, 0, DIM, DIM, 0 };
        gemm_tc<<<dim3(16, 4), 128, 0, s2>>>(go2);
    }
    cudaEventRecord(e_done, s2);
    cudaStreamWaitEvent(0, e_done, 0);
    copy_kernel<<<(NLAY * BH) / 256, 256>>>(h_, out_h, NLAY * BH);
}

// round 10
// speedup vs baseline: 3.7060x; 1.0073x over previous
#include <cuda_runtime.h>
#include <cuda_bf16.h>
#include <math.h>

#define BATCH 256
#define TOUT  36
#define SIN   96
#define SINP  128
#define DIM   1024
#define HID   1024
#define NLAY  2

typedef __nv_bfloat16 bf16;

#define BH      (BATCH * HID)
#define PAR     (2 * BH)
#define XOFF    ((size_t)BATCH * TOUT * DIM)
#define WIH_OFF ((size_t)NLAY * 3 * HID * DIM)
#define WHH_OFF ((size_t)NLAY * 3 * HID * HID)
#define SROW    40

// ---------------- scratch ----------------
__device__ float g_h[NLAY * BATCH * HID];
__device__ bf16  g_hd0[2 * BATCH * HID];
__device__ bf16  g_hd1[2][2 * BATCH * HID];
__device__ bf16  g_xd[2 * (size_t)BATCH * TOUT * DIM];
__device__ bf16  g_xcd[2 * BATCH * DIM];
__device__ bf16  g_wencd[2 * BATCH * HID];
__device__ bf16  g_tmpd[2 * BATCH * DIM];
__device__ float g_logits[BATCH * SIN];
__device__ float g_gi[BATCH * 3 * HID];
__device__ float g_gh0[BATCH * 3 * HID];
__device__ float g_gh1[BATCH * 3 * HID];
__device__ bf16 g_attnWd[2 * SINP * (DIM + HID)];
__device__ bf16 g_combWd[2 * DIM * (DIM + HID)];
__device__ bf16 g_Wihd[2 * NLAY * 3 * HID * DIM];
__device__ bf16 g_Whhd[2 * NLAY * 3 * HID * HID];
__device__ bf16 g_out1d[2 * DIM * HID];
__device__ bf16 g_out2d[2 * DIM * DIM];

// ---------------- helpers ----------------
__device__ __forceinline__ void dec2(float v, bf16& hi, bf16& lo) {
    hi = __float2bfloat16(v);
    lo = __float2bfloat16(v - __bfloat162float(hi));
}

__device__ __forceinline__ void mma_bf16(float c[4], const unsigned a[4], const unsigned b0, const unsigned b1) {
    asm volatile(
        "mma.sync.aligned.m16n8k16.row.col.f32.bf16.bf16.f32 "
        "{%0,%1,%2,%3},{%4,%5,%6,%7},{%8,%9},{%0,%1,%2,%3};\n"
        : "+f"(c[0]), "+f"(c[1]), "+f"(c[2]), "+f"(c[3])
        : "r"(a[0]), "r"(a[1]), "r"(a[2]), "r"(a[3]), "r"(b0), "r"(b1));
}

__device__ __forceinline__ void ldsm4(unsigned r[4], unsigned addr) {
    asm volatile("ldmatrix.sync.aligned.m8n8.x4.shared.b16 {%0,%1,%2,%3}, [%4];"
                 : "=r"(r[0]), "=r"(r[1]), "=r"(r[2]), "=r"(r[3]) : "r"(addr));
}

__device__ __forceinline__ void cpa16(unsigned dst, const void* src) {
    asm volatile("cp.async.cg.shared.global [%0], [%1], 16;" :: "r"(dst), "l"(src));
}

// ---------------- gemm argument bundle ----------------
struct GArg {
    const bf16* A0; size_t aoff0; int lda0; int K0;
    const bf16* A1; size_t aoff1; int lda1;
    const bf16* Wd; size_t woff;
    const float* bias;
    float* C; int ldc;
    bf16* Cd; size_t cdoff; int ldcd;
    int N; int K; int act;
};

// ---------------- generic tensor-core GEMM (BM=64,BN=64,BK=32) ------------
__device__ __forceinline__ void gemm_body(const GArg& g)
{
    __shared__ __align__(16) bf16 As[2][2][64 * SROW];
    __shared__ __align__(16) bf16 Ws[2][2][64 * SROW];

    const int tid = threadIdx.x, lane = tid & 31, warp = tid >> 5;
    const int wm = (warp >> 1) * 32, wn = (warp & 1) * 32;
    const int rowBase = blockIdx.y * 64, colBase = blockIdx.x * 64;

    const int r0c = tid >> 2, c0c = (tid & 3) * 8;
    const int r1c = (tid + 128) >> 2, c1c = c0c;

    float acc[2][4][4];
#pragma unroll
    for (int mt = 0; mt < 2; mt++)
#pragma unroll
        for (int nt = 0; nt < 4; nt++)
#pragma unroll
            for (int q = 0; q < 4; q++) acc[mt][nt][q] = 0.f;

    const int nsteps = g.K >> 5;

    auto prefetch = [&](int s, int buf) {
        int k0 = s << 5;
        const bf16* Ab; size_t ao; int lda, kk;
        if (k0 < g.K0) { Ab = g.A0; ao = g.aoff0; lda = g.lda0; kk = k0; }
        else           { Ab = g.A1; ao = g.aoff1; lda = g.lda1; kk = k0 - g.K0; }
        {
            const bf16* p0 = Ab + (size_t)(rowBase + r0c) * lda + kk + c0c;
            const bf16* p1 = Ab + (size_t)(rowBase + r1c) * lda + kk + c1c;
            cpa16((unsigned)__cvta_generic_to_shared(&As[buf][0][r0c * SROW + c0c]), p0);
            cpa16((unsigned)__cvta_generic_to_shared(&As[buf][0][r1c * SROW + c1c]), p1);
            cpa16((unsigned)__cvta_generic_to_shared(&As[buf][1][r0c * SROW + c0c]), p0 + ao);
            cpa16((unsigned)__cvta_generic_to_shared(&As[buf][1][r1c * SROW + c1c]), p1 + ao);
        }
        {
            const bf16* p0 = g.Wd + (size_t)(colBase + r0c) * g.K + k0 + c0c;
            const bf16* p1 = g.Wd + (size_t)(colBase + r1c) * g.K + k0 + c1c;
            cpa16((unsigned)__cvta_generic_to_shared(&Ws[buf][0][r0c * SROW + c0c]), p0);
            cpa16((unsigned)__cvta_generic_to_shared(&Ws[buf][0][r1c * SROW + c1c]), p1);
            cpa16((unsigned)__cvta_generic_to_shared(&Ws[buf][1][r0c * SROW + c0c]), p0 + g.woff);
            cpa16((unsigned)__cvta_generic_to_shared(&Ws[buf][1][r1c * SROW + c1c]), p1 + g.woff);
        }
        asm volatile("cp.async.commit_group;");
    };

    prefetch(0, 0);

    const int aRow = lane & 15, aCol = (lane >> 4) << 3;
    const int bRow = ((lane >> 4) << 3) + (lane & 7), bCol = ((lane >> 3) & 1) << 3;

    for (int s = 0; s < nsteps; s++) {
        int buf = s & 1;
        if (s + 1 < nsteps) {
            prefetch(s + 1, buf ^ 1);
            asm volatile("cp.async.wait_group 1;");
        } else {
            asm volatile("cp.async.wait_group 0;");
        }
        __syncthreads();

#pragma unroll
        for (int h = 0; h < 2; h++) {
            int kk16 = h << 4;
            unsigned ah[2][4], al[2][4], bh[2][4], bl[2][4];
#pragma unroll
            for (int mt = 0; mt < 2; mt++) {
                int ro = (wm + mt * 16 + aRow) * SROW + kk16 + aCol;
                ldsm4(ah[mt], (unsigned)__cvta_generic_to_shared(&As[buf][0][ro]));
                ldsm4(al[mt], (unsigned)__cvta_generic_to_shared(&As[buf][1][ro]));
            }
#pragma unroll
            for (int np = 0; np < 2; np++) {
                int ro = (wn + np * 16 + bRow) * SROW + kk16 + bCol;
                ldsm4(bh[np], (unsigned)__cvta_generic_to_shared(&Ws[buf][0][ro]));
                ldsm4(bl[np], (unsigned)__cvta_generic_to_shared(&Ws[buf][1][ro]));
            }
#pragma unroll
            for (int mt = 0; mt < 2; mt++)
#pragma unroll
                for (int nt = 0; nt < 4; nt++) {
                    int np = nt >> 1, q = (nt & 1) * 2;
                    mma_bf16(acc[mt][nt], ah[mt], bh[np][q], bh[np][q + 1]);
                    mma_bf16(acc[mt][nt], ah[mt], bl[np][q], bl[np][q + 1]);
                    mma_bf16(acc[mt][nt], al[mt], bh[np][q], bh[np][q + 1]);
                }
        }
        __syncthreads();
    }

#pragma unroll
    for (int mt = 0; mt < 2; mt++)
#pragma unroll
        for (int nt = 0; nt < 4; nt++) {
            int r0 = rowBase + wm + mt * 16 + (lane >> 2);
            int c0 = colBase + wn + nt * 8 + (lane & 3) * 2;
            if (c0 >= g.N) continue;
            float b0 = g.bias ? g.bias[c0] : 0.f;
            float b1 = g.bias ? g.bias[c0 + 1] : 0.f;
#pragma unroll
            for (int p = 0; p < 2; p++) {
                int r = r0 + p * 8;
                float v0 = acc[mt][nt][p * 2] + b0;
                float v1 = acc[mt][nt][p * 2 + 1] + b1;
                if (g.act == 1) { v0 = fmaxf(v0, 0.f); v1 = fmaxf(v1, 0.f); }
                if (g.C) {
                    g.C[(size_t)r * g.ldc + c0] = v0;
                    g.C[(size_t)r * g.ldc + c0 + 1] = v1;
                }
                if (g.Cd) {
                    bf16 h0, l0, h1, l1;
                    dec2(v0, h0, l0);
                    dec2(v1, h1, l1);
                    size_t o = (size_t)r * g.ldcd + c0;
                    g.Cd[o] = h0; g.Cd[o + 1] = h1;
                    g.Cd[g.cdoff + o] = l0; g.Cd[g.cdoff + o + 1] = l1;
                }
            }
        }
}

__global__ __launch_bounds__(128) void gemm_tc(GArg g)          { gemm_body(g); }
__global__ __launch_bounds__(128) void gemm_tc2(GArg a, GArg b) { gemm_body(blockIdx.z ? b : a); }

// ---------------- fused gi-GEMM + GRU gate (grouped-N) ---------------------
// BM=32 (grid.y=8), per-group BN=64 (grid.x=16), 3 gate groups per CTA.
// A (bf16 hi/lo), W rows at g*1024 + col, K=1024. Epilogue computes the GRU
// gate using gh (precomputed) and h_prev, writes h + hd decomposition.
#define GSROW 40
#define GIGATE_SMEM ((2*2*32*GSROW + 2*2*3*64*GSROW) * (int)sizeof(bf16))
__global__ __launch_bounds__(128) void gemm_gigate(
    const bf16* __restrict__ A, size_t aoff, int lda,
    const bf16* __restrict__ Wd, size_t woff,
    const float* __restrict__ bias,
    const float* __restrict__ gh,
    float* __restrict__ h, bf16* __restrict__ hd, int K)
{
    extern __shared__ __align__(16) bf16 dsm[];
    bf16* AsB = dsm;                         // [buf][hl][32*GSROW]
    bf16* WsB = dsm + 2 * 2 * 32 * GSROW;    // [buf][hl][g][64*GSROW]

    const int tid = threadIdx.x, lane = tid & 31, warp = tid >> 5;
    const int wn = warp * 16;
    const int rowBase = blockIdx.y * 32, colBase = blockIdx.x * 64;

    float acc[3][2][2][4];
#pragma unroll
    for (int gg = 0; gg < 3; gg++)
#pragma unroll
        for (int mt = 0; mt < 2; mt++)
#pragma unroll
            for (int nt = 0; nt < 2; nt++)
#pragma unroll
                for (int q = 0; q < 4; q++) acc[gg][mt][nt][q] = 0.f;

    const int rA = tid >> 2, cA = (tid & 3) * 8;
    const int r1c = rA + 32;
    const int nsteps = K >> 5;

    auto As = [&](int buf, int hl) { return AsB + (buf * 2 + hl) * 32 * GSROW; };
    auto Ws = [&](int buf, int hl, int gg) { return WsB + ((buf * 2 + hl) * 3 + gg) * 64 * GSROW; };

    auto prefetch = [&](int s, int buf) {
        int k0 = s << 5;
        const bf16* pa = A + (size_t)(rowBase + rA) * lda + k0 + cA;
        cpa16((unsigned)__cvta_generic_to_shared(As(buf, 0) + rA * GSROW + cA), pa);
        cpa16((unsigned)__cvta_generic_to_shared(As(buf, 1) + rA * GSROW + cA), pa + aoff);
#pragma unroll
        for (int gg = 0; gg < 3; gg++) {
            const bf16* p0 = Wd + (size_t)(gg * 1024 + colBase + rA) * K + k0 + cA;
            const bf16* p1 = Wd + (size_t)(gg * 1024 + colBase + r1c) * K + k0 + cA;
            cpa16((unsigned)__cvta_generic_to_shared(Ws(buf, 0, gg) + rA * GSROW + cA), p0);
            cpa16((unsigned)__cvta_generic_to_shared(Ws(buf, 0, gg) + r1c * GSROW + cA), p1);
            cpa16((unsigned)__cvta_generic_to_shared(Ws(buf, 1, gg) + rA * GSROW + cA), p0 + woff);
            cpa16((unsigned)__cvta_generic_to_shared(Ws(buf, 1, gg) + r1c * GSROW + cA), p1 + woff);
        }
        asm volatile("cp.async.commit_group;");
    };

    prefetch(0, 0);

    const int aRow = lane & 15, aCol = (lane >> 4) << 3;
    const int bRow = ((lane >> 4) << 3) + (lane & 7), bCol = ((lane >> 3) & 1) << 3;

    for (int s = 0; s < nsteps; s++) {
        int buf = s & 1;
        if (s + 1 < nsteps) {
            prefetch(s + 1, buf ^ 1);
            asm volatile("cp.async.wait_group 1;");
        } else {
            asm volatile("cp.async.wait_group 0;");
        }
        __syncthreads();

#pragma unroll
        for (int hh = 0; hh < 2; hh++) {
            int kk16 = hh << 4;
            unsigned ah[2][4], al[2][4], bh[3][4], bl[3][4];
#pragma unroll
            for (int mt = 0; mt < 2; mt++) {
                int ro = (mt * 16 + aRow) * GSROW + kk16 + aCol;
                ldsm4(ah[mt], (unsigned)__cvta_generic_to_shared(As(buf, 0) + ro));
                ldsm4(al[mt], (unsigned)__cvta_generic_to_shared(As(buf, 1) + ro));
            }
#pragma unroll
            for (int gg = 0; gg < 3; gg++) {
                int ro = (wn + bRow) * GSROW + kk16 + bCol;
                ldsm4(bh[gg], (unsigned)__cvta_generic_to_shared(Ws(buf, 0, gg) + ro));
                ldsm4(bl[gg], (unsigned)__cvta_generic_to_shared(Ws(buf, 1, gg) + ro));
            }
#pragma unroll
            for (int gg = 0; gg < 3; gg++)
#pragma unroll
                for (int mt = 0; mt < 2; mt++)
#pragma unroll
                    for (int nt = 0; nt < 2; nt++) {
                        int q = nt * 2;
                        mma_bf16(acc[gg][mt][nt], ah[mt], bh[gg][q], bh[gg][q + 1]);
                        mma_bf16(acc[gg][mt][nt], ah[mt], bl[gg][q], bl[gg][q + 1]);
                        mma_bf16(acc[gg][mt][nt], al[mt], bh[gg][q], bh[gg][q + 1]);
                    }
        }
        __syncthreads();
    }

    // fused GRU gate epilogue
#pragma unroll
    for (int mt = 0; mt < 2; mt++)
#pragma unroll
        for (int nt = 0; nt < 2; nt++) {
            int r0 = rowBase + mt * 16 + (lane >> 2);
            int c0 = colBase + wn + nt * 8 + (lane & 3) * 2;
#pragma unroll
            for (int p = 0; p < 2; p++) {
                int r = r0 + p * 8;
                const float* ghr = gh + (size_t)r * 3072;
#pragma unroll
                for (int cc = 0; cc < 2; cc++) {
                    int c = c0 + cc;
                    float ir  = acc[0][mt][nt][p * 2 + cc] + bias[c];
                    float iz  = acc[1][mt][nt][p * 2 + cc] + bias[1024 + c];
                    float in_ = acc[2][mt][nt][p * 2 + cc] + bias[2048 + c];
                    float hr = ghr[c], hz = ghr[1024 + c], hn = ghr[2048 + c];
                    float rg = 1.f / (1.f + expf(-(ir + hr)));
                    float zg = 1.f / (1.f + expf(-(iz + hz)));
                    float ng = tanhf(in_ + rg * hn);
                    int idx = r * 1024 + c;
                    float v = (1.f - zg) * ng + zg * h[idx];
                    h[idx] = v;
                    bf16 hi, lo;
                    dec2(v, hi, lo);
                    hd[idx] = hi;
                    hd[BH + idx] = lo;
                }
            }
        }
}

// ---------------- decomposition / init ----------------
__global__ void decomp_kernel(const float* __restrict__ src, bf16* __restrict__ dst,
                              size_t off, int n)
{
    int i = blockIdx.x * 256 + threadIdx.x;
    if (i < n) {
        bf16 hi, lo;
        dec2(src[i], hi, lo);
        dst[i] = hi;
        dst[off + i] = lo;
    }
}

__global__ void init_h_kernel(const float* __restrict__ hidden,
                              float* __restrict__ h,
                              bf16* __restrict__ hd0, bf16* __restrict__ hd1init)
{
    int i = blockIdx.x * 256 + threadIdx.x;
    float v = hidden[i];
    h[i] = v;
    int l = i >> 18;
    int j = i & (BH - 1);
    bf16* hd = l ? hd1init : hd0;
    bf16 hi, lo;
    dec2(v, hi, lo);
    hd[j] = hi;
    hd[BH + j] = lo;
}

__global__ void copy_kernel(const float* __restrict__ src, float* __restrict__ dst, int n)
{
    int i = blockIdx.x * 256 + threadIdx.x;
    if (i < n) dst[i] = src[i];
}

// ---------------- fused softmax + wenc ----------------
__global__ void softwenc_kernel(const float* __restrict__ logits,
                                const float* __restrict__ enc,
                                float* __restrict__ out_attn, int t,
                                bf16* __restrict__ wencd)
{
    __shared__ float sm[256];
    __shared__ float a[SIN];
    int b = blockIdx.x, tid = threadIdx.x;
    float v = (tid < SIN) ? logits[b * SIN + tid] : -1e30f;
    sm[tid] = v; __syncthreads();
    for (int s = 128; s > 0; s >>= 1) {
        if (tid < s) sm[tid] = fmaxf(sm[tid], sm[tid + s]);
        __syncthreads();
    }
    float mx = sm[0]; __syncthreads();
    float e = (tid < SIN) ? expf(v - mx) : 0.f;
    sm[tid] = e; __syncthreads();
    for (int s = 128; s > 0; s >>= 1) {
        if (tid < s) sm[tid] += sm[tid + s];
        __syncthreads();
    }
    float inv = 1.f / sm[0];
    if (tid < SIN) {
        float aa = e * inv;
        a[tid] = aa;
        out_attn[(size_t)b * TOUT * SIN + (size_t)t * SIN + tid] = aa;
    }
    __syncthreads();

    // wenc: 256 threads x float4 = 1024 h
    const float4* ep = reinterpret_cast<const float4*>(enc + (size_t)b * SIN * HID) + tid;
    float ax = 0.f, ay = 0.f, az = 0.f, aww = 0.f;
#pragma unroll 4
    for (int s = 0; s < SIN; s++) {
        float4 vv = ep[(size_t)s * (HID / 4)];
        float w = a[s];
        ax = fmaf(w, vv.x, ax); ay = fmaf(w, vv.y, ay);
        az = fmaf(w, vv.z, az); aww = fmaf(w, vv.w, aww);
    }
    int idx = b * HID + tid * 4;
    float r4[4] = {ax, ay, az, aww};
#pragma unroll
    for (int q = 0; q < 4; q++) {
        bf16 hi, lo;
        dec2(r4[q], hi, lo);
        wencd[idx + q] = hi;
        wencd[BH + idx + q] = lo;
    }
}

// ---------------- host orchestration ----------------
extern "C" void kernel_launch(void* const* d_in, const int* in_sizes, int n_in,
                              void* d_out, int out_size)
{
    const float* target = (const float*)d_in[0];
    const float* hidden = (const float*)d_in[1];
    const float* enc    = (const float*)d_in[2];
    const float* attn_W = (const float*)d_in[3];
    const float* attn_b = (const float*)d_in[4];
    const float* comb_W = (const float*)d_in[5];
    const float* comb_b = (const float*)d_in[6];
    const float* W_ih   = (const float*)d_in[7];
    const float* W_hh   = (const float*)d_in[8];
    const float* b_ih   = (const float*)d_in[9];
    const float* b_hh   = (const float*)d_in[10];
    const float* out1_W = (const float*)d_in[11];
    const float* out1_b = (const float*)d_in[12];
    const float* out2_W = (const float*)d_in[13];
    const float* out2_b = (const float*)d_in[14];

    float* out   = (float*)d_out;
    float* out_y = out;
    float* out_h = out + (size_t)BATCH * TOUT * DIM;
    float* out_a = out_h + (size_t)NLAY * BATCH * HID;

    float *h_, *logits, *gi, *gh0b, *gh1b;
    bf16 *hd0, *hd1, *xd, *xcd, *wencd, *tmpd;
    bf16 *attnWd, *combWd, *Wihd, *Whhd, *out1d, *out2d;
    cudaGetSymbolAddress((void**)&h_,     g_h);
    cudaGetSymbolAddress((void**)&hd0,    g_hd0);
    cudaGetSymbolAddress((void**)&hd1,    g_hd1);
    cudaGetSymbolAddress((void**)&xd,     g_xd);
    cudaGetSymbolAddress((void**)&xcd,    g_xcd);
    cudaGetSymbolAddress((void**)&wencd,  g_wencd);
    cudaGetSymbolAddress((void**)&tmpd,   g_tmpd);
    cudaGetSymbolAddress((void**)&logits, g_logits);
    cudaGetSymbolAddress((void**)&gi,     g_gi);
    cudaGetSymbolAddress((void**)&gh0b,   g_gh0);
    cudaGetSymbolAddress((void**)&gh1b,   g_gh1);
    cudaGetSymbolAddress((void**)&attnWd, g_attnWd);
    cudaGetSymbolAddress((void**)&combWd, g_combWd);
    cudaGetSymbolAddress((void**)&Wihd,   g_Wihd);
    cudaGetSymbolAddress((void**)&Whhd,   g_Whhd);
    cudaGetSymbolAddress((void**)&out1d,  g_out1d);
    cudaGetSymbolAddress((void**)&out2d,  g_out2d);

    static cudaStream_t s2 = nullptr;
    static cudaEvent_t e_g1 = nullptr, e_gh = nullptr, e_done = nullptr;
    if (!s2) {
        cudaStreamCreateWithFlags(&s2, cudaStreamNonBlocking);
        cudaEventCreateWithFlags(&e_g1,   cudaEventDisableTiming);
        cudaEventCreateWithFlags(&e_gh,   cudaEventDisableTiming);
        cudaEventCreateWithFlags(&e_done, cudaEventDisableTiming);
        cudaFuncSetAttribute(gemm_gigate, cudaFuncAttributeMaxDynamicSharedMemorySize,
                             GIGATE_SMEM);
    }

    // prologue
    {
        int n;
        n = SIN * (DIM + HID);
        decomp_kernel<<<(n + 255) / 256, 256>>>(attn_W, attnWd, (size_t)SINP * (DIM + HID), n);
        n = DIM * (DIM + HID);
        decomp_kernel<<<(n + 255) / 256, 256>>>(comb_W, combWd, n, n);
        n = NLAY * 3 * HID * DIM;
        decomp_kernel<<<(n + 255) / 256, 256>>>(W_ih, Wihd, n, n);
        n = NLAY * 3 * HID * HID;
        decomp_kernel<<<(n + 255) / 256, 256>>>(W_hh, Whhd, n, n);
        n = DIM * HID;
        decomp_kernel<<<(n + 255) / 256, 256>>>(out1_W, out1d, n, n);
        n = DIM * DIM;
        decomp_kernel<<<(n + 255) / 256, 256>>>(out2_W, out2d, n, n);
        n = (int)(BATCH * TOUT * DIM);
        decomp_kernel<<<(n + 255) / 256, 256>>>(target, xd, XOFF, n);
        init_h_kernel<<<(NLAY * BH) / 256, 256>>>(hidden, h_, hd0, hd1 + PAR);
    }
    cudaEventRecord(e_g1, 0);

    const int LDX = TOUT * DIM;
    const size_t BD = (size_t)BATCH * DIM;

    for (int t = 0; t < TOUT; t++) {
        bf16* hd1_rd = hd1 + ((t - 1) & 1) * (size_t)PAR;
        bf16* hd1_wr = hd1 + (t & 1) * (size_t)PAR;
        const bf16* xt = xd + (size_t)t * DIM;

        // ---- stream2: gh pair for step t, then out-head for step t-1 ----
        cudaStreamWaitEvent(s2, e_g1, 0);
        GArg gh0a = { hd0, BH, HID, HID, nullptr, 0, 0,
                      Whhd, WHH_OFF, b_hh, gh0b, 3 * HID,
                      nullptr, 0, 0, 3 * HID, HID, 0 };
        GArg gh1a = { hd1_rd, BH, HID, HID, nullptr, 0, 0,
                      Whhd + (size_t)3 * HID * HID, WHH_OFF, b_hh + 3 * HID,
                      gh1b, 3 * HID, nullptr, 0, 0, 3 * HID, HID, 0 };
        gemm_tc2<<<dim3(48, 4, 2), 128, 0, s2>>>(gh0a, gh1a);
        cudaEventRecord(e_gh, s2);
        if (t > 0) {
            bf16* hprev = hd1 + ((t - 1) & 1) * (size_t)PAR;
            GArg go1 = { hprev, BH, HID, HID, nullptr, 0, 0,
                         out1d, (size_t)DIM * HID, out1_b,
                         nullptr, 0, tmpd, BD, DIM, DIM, HID, 0 };
            gemm_tc<<<dim3(16, 4), 128, 0, s2>>>(go1);
            GArg go2 = { tmpd, BD, DIM, DIM, nullptr, 0, 0,
                         out2d, (size_t)DIM * DIM, out2_b,
                         out_y + (size_t)(t - 1) * DIM, LDX,
                         nullptr, 0, 0, DIM, DIM, 0 };
            gemm_tc<<<dim3(16, 4), 128, 0, s2>>>(go2);
        }

        // ---- stream1 (default): attn -> softwenc -> comb -> gi0gate -> gi1gate
        GArg ga = { xt, XOFF, LDX, DIM, hd1_rd, BH, HID,
                    attnWd, (size_t)SINP * (DIM + HID), attn_b,
                    logits, SIN, nullptr, 0, 0, SIN, DIM + HID, 0 };
        gemm_tc<<<dim3(2, 4), 128>>>(ga);
        softwenc_kernel<<<BATCH, 256>>>(logits, enc, out_a, t, wencd);

        GArg gc = { xt, XOFF, LDX, DIM, wencd, BH, HID,
                    combWd, (size_t)DIM * (DIM + HID), comb_b,
                    nullptr, 0, xcd, BD, DIM, DIM, DIM + HID, 1 };
        gemm_tc<<<dim3(16, 4), 128>>>(gc);

        cudaStreamWaitEvent(0, e_gh, 0);
        gemm_gigate<<<dim3(16, 8), 128, GIGATE_SMEM>>>(
            xcd, BD, DIM, Wihd, WIH_OFF, b_ih, gh0b, h_, hd0, DIM);
        gemm_gigate<<<dim3(16, 8), 128, GIGATE_SMEM>>>(
            hd0, BH, HID, Wihd + (size_t)3 * HID * DIM, WIH_OFF,
            b_ih + 3 * HID, gh1b, h_ + BH, hd1_wr, HID);
        cudaEventRecord(e_g1, 0);
    }

    // tail: out-head for t=35 on stream2, then join + final hidden copy
    cudaStreamWaitEvent(s2, e_g1, 0);
    {
        bf16* hlast = hd1 + ((TOUT - 1) & 1) * (size_t)PAR;
        GArg go1 = { hlast, BH, HID, HID, nullptr, 0, 0,
                     out1d, (size_t)DIM * HID, out1_b,
                     nullptr, 0, tmpd, BD, DIM, DIM, HID, 0 };
        gemm_tc<<<dim3(16, 4), 128, 0, s2>>>(go1);
        GArg go2 = { tmpd, BD, DIM, DIM, nullptr, 0, 0,
                     out2d, (size_t)DIM * DIM, out2_b,
                     out_y + (size_t)(TOUT - 1) * DIM, LDX,
                     nullptr, 0, 0, DIM, DIM, 0 };
        gemm_tc<<<dim3(16, 4), 128, 0, s2>>>(go2);
    }
    cudaEventRecord(e_done, s2);
    cudaStreamWaitEvent(0, e_done, 0);
    copy_kernel<<<(NLAY * BH) / 256, 256>>>(h_, out_h, NLAY * BH);
}

// round 13
// speedup vs baseline: 4.1913x; 1.1310x over previous
#include <cuda_runtime.h>
#include <cuda_bf16.h>
#include <math.h>

#define BATCH 256
#define TOUT  36
#define SIN   96
#define SINP  128
#define DIM   1024
#define HID   1024
#define NLAY  2
#define NSPLIT 8

typedef __nv_bfloat16 bf16;

#define BH      (BATCH * HID)
#define PAR     (2 * BH)
#define XOFF    ((size_t)BATCH * TOUT * DIM)
#define WIH_OFF ((size_t)NLAY * 3 * HID * DIM)
#define WHH_OFF ((size_t)NLAY * 3 * HID * HID)
#define SROW    40

// ---------------- scratch ----------------
__device__ float g_h[NLAY * BATCH * HID];
__device__ bf16  g_hd0[2 * BATCH * HID];
__device__ bf16  g_hd1[2][2 * BATCH * HID];
__device__ bf16  g_xd[2 * (size_t)BATCH * TOUT * DIM];
__device__ bf16  g_xcd[2 * BATCH * DIM];
__device__ bf16  g_wencd[2 * BATCH * HID];
__device__ bf16  g_tmpd[2 * BATCH * DIM];
__device__ float g_attnP[NSPLIT * BATCH * SIN];
__device__ float g_gh0[BATCH * 3 * HID];
__device__ float g_gh1[BATCH * 3 * HID];
__device__ bf16 g_attnWd[2 * SINP * (DIM + HID)];
__device__ bf16 g_combWd[2 * DIM * (DIM + HID)];
__device__ bf16 g_Wihd[2 * NLAY * 3 * HID * DIM];
__device__ bf16 g_Whhd[2 * NLAY * 3 * HID * HID];
__device__ bf16 g_out1d[2 * DIM * HID];
__device__ bf16 g_out2d[2 * DIM * DIM];

// ---------------- helpers ----------------
__device__ __forceinline__ void dec2(float v, bf16& hi, bf16& lo) {
    hi = __float2bfloat16(v);
    lo = __float2bfloat16(v - __bfloat162float(hi));
}

__device__ __forceinline__ void mma_bf16(float c[4], const unsigned a[4], const unsigned b0, const unsigned b1) {
    asm volatile(
        "mma.sync.aligned.m16n8k16.row.col.f32.bf16.bf16.f32 "
        "{%0,%1,%2,%3},{%4,%5,%6,%7},{%8,%9},{%0,%1,%2,%3};\n"
        : "+f"(c[0]), "+f"(c[1]), "+f"(c[2]), "+f"(c[3])
        : "r"(a[0]), "r"(a[1]), "r"(a[2]), "r"(a[3]), "r"(b0), "r"(b1));
}

__device__ __forceinline__ void ldsm4(unsigned r[4], unsigned addr) {
    asm volatile("ldmatrix.sync.aligned.m8n8.x4.shared.b16 {%0,%1,%2,%3}, [%4];"
                 : "=r"(r[0]), "=r"(r[1]), "=r"(r[2]), "=r"(r[3]) : "r"(addr));
}

__device__ __forceinline__ void cpa16(unsigned dst, const void* src) {
    asm volatile("cp.async.cg.shared.global [%0], [%1], 16;" :: "r"(dst), "l"(src));
}

// ---------------- gemm argument bundle ----------------
struct GArg {
    const bf16* A0; size_t aoff0; int lda0; int K0;
    const bf16* A1; size_t aoff1; int lda1;
    const bf16* Wd; size_t woff;
    const float* bias;
    float* C; int ldc;
    bf16* Cd; size_t cdoff; int ldcd;
    int N; int K; int kw; int act;   // kw = W row stride (elements)
};

// ---------------- generic tensor-core GEMM (BM=64,BN=64,BK=32) ------------
__device__ __forceinline__ void gemm_body(const GArg& g)
{
    __shared__ __align__(16) bf16 As[2][2][64 * SROW];
    __shared__ __align__(16) bf16 Ws[2][2][64 * SROW];

    const int tid = threadIdx.x, lane = tid & 31, warp = tid >> 5;
    const int wm = (warp >> 1) * 32, wn = (warp & 1) * 32;
    const int rowBase = blockIdx.y * 64, colBase = blockIdx.x * 64;

    const int r0c = tid >> 2, c0c = (tid & 3) * 8;
    const int r1c = (tid + 128) >> 2, c1c = c0c;

    float acc[2][4][4];
#pragma unroll
    for (int mt = 0; mt < 2; mt++)
#pragma unroll
        for (int nt = 0; nt < 4; nt++)
#pragma unroll
            for (int q = 0; q < 4; q++) acc[mt][nt][q] = 0.f;

    const int nsteps = g.K >> 5;

    auto prefetch = [&](int s, int buf) {
        int k0 = s << 5;
        const bf16* Ab; size_t ao; int lda, kk;
        if (k0 < g.K0) { Ab = g.A0; ao = g.aoff0; lda = g.lda0; kk = k0; }
        else           { Ab = g.A1; ao = g.aoff1; lda = g.lda1; kk = k0 - g.K0; }
        {
            const bf16* p0 = Ab + (size_t)(rowBase + r0c) * lda + kk + c0c;
            const bf16* p1 = Ab + (size_t)(rowBase + r1c) * lda + kk + c1c;
            cpa16((unsigned)__cvta_generic_to_shared(&As[buf][0][r0c * SROW + c0c]), p0);
            cpa16((unsigned)__cvta_generic_to_shared(&As[buf][0][r1c * SROW + c1c]), p1);
            cpa16((unsigned)__cvta_generic_to_shared(&As[buf][1][r0c * SROW + c0c]), p0 + ao);
            cpa16((unsigned)__cvta_generic_to_shared(&As[buf][1][r1c * SROW + c1c]), p1 + ao);
        }
        {
            const bf16* p0 = g.Wd + (size_t)(colBase + r0c) * g.kw + k0 + c0c;
            const bf16* p1 = g.Wd + (size_t)(colBase + r1c) * g.kw + k0 + c1c;
            cpa16((unsigned)__cvta_generic_to_shared(&Ws[buf][0][r0c * SROW + c0c]), p0);
            cpa16((unsigned)__cvta_generic_to_shared(&Ws[buf][0][r1c * SROW + c1c]), p1);
            cpa16((unsigned)__cvta_generic_to_shared(&Ws[buf][1][r0c * SROW + c0c]), p0 + g.woff);
            cpa16((unsigned)__cvta_generic_to_shared(&Ws[buf][1][r1c * SROW + c1c]), p1 + g.woff);
        }
        asm volatile("cp.async.commit_group;");
    };

    prefetch(0, 0);

    const int aRow = lane & 15, aCol = (lane >> 4) << 3;
    const int bRow = ((lane >> 4) << 3) + (lane & 7), bCol = ((lane >> 3) & 1) << 3;

    for (int s = 0; s < nsteps; s++) {
        int buf = s & 1;
        if (s + 1 < nsteps) {
            prefetch(s + 1, buf ^ 1);
            asm volatile("cp.async.wait_group 1;");
        } else {
            asm volatile("cp.async.wait_group 0;");
        }
        __syncthreads();

#pragma unroll
        for (int h = 0; h < 2; h++) {
            int kk16 = h << 4;
            unsigned ah[2][4], al[2][4], bh[2][4], bl[2][4];
#pragma unroll
            for (int mt = 0; mt < 2; mt++) {
                int ro = (wm + mt * 16 + aRow) * SROW + kk16 + aCol;
                ldsm4(ah[mt], (unsigned)__cvta_generic_to_shared(&As[buf][0][ro]));
                ldsm4(al[mt], (unsigned)__cvta_generic_to_shared(&As[buf][1][ro]));
            }
#pragma unroll
            for (int np = 0; np < 2; np++) {
                int ro = (wn + np * 16 + bRow) * SROW + kk16 + bCol;
                ldsm4(bh[np], (unsigned)__cvta_generic_to_shared(&Ws[buf][0][ro]));
                ldsm4(bl[np], (unsigned)__cvta_generic_to_shared(&Ws[buf][1][ro]));
            }
#pragma unroll
            for (int mt = 0; mt < 2; mt++)
#pragma unroll
                for (int nt = 0; nt < 4; nt++) {
                    int np = nt >> 1, q = (nt & 1) * 2;
                    mma_bf16(acc[mt][nt], ah[mt], bh[np][q], bh[np][q + 1]);
                    mma_bf16(acc[mt][nt], ah[mt], bl[np][q], bl[np][q + 1]);
                    mma_bf16(acc[mt][nt], al[mt], bh[np][q], bh[np][q + 1]);
                }
        }
        __syncthreads();
    }

#pragma unroll
    for (int mt = 0; mt < 2; mt++)
#pragma unroll
        for (int nt = 0; nt < 4; nt++) {
            int r0 = rowBase + wm + mt * 16 + (lane >> 2);
            int c0 = colBase + wn + nt * 8 + (lane & 3) * 2;
            if (c0 >= g.N) continue;
            float b0 = g.bias ? g.bias[c0] : 0.f;
            float b1 = g.bias ? g.bias[c0 + 1] : 0.f;
#pragma unroll
            for (int p = 0; p < 2; p++) {
                int r = r0 + p * 8;
                float v0 = acc[mt][nt][p * 2] + b0;
                float v1 = acc[mt][nt][p * 2 + 1] + b1;
                if (g.act == 1) { v0 = fmaxf(v0, 0.f); v1 = fmaxf(v1, 0.f); }
                if (g.C) {
                    g.C[(size_t)r * g.ldc + c0] = v0;
                    g.C[(size_t)r * g.ldc + c0 + 1] = v1;
                }
                if (g.Cd) {
                    bf16 h0, l0, h1, l1;
                    dec2(v0, h0, l0);
                    dec2(v1, h1, l1);
                    size_t o = (size_t)r * g.ldcd + c0;
                    g.Cd[o] = h0; g.Cd[o + 1] = h1;
                    g.Cd[g.cdoff + o] = l0; g.Cd[g.cdoff + o + 1] = l1;
                }
            }
        }
}

__global__ __launch_bounds__(128) void gemm_tc(GArg g)          { gemm_body(g); }
__global__ __launch_bounds__(128) void gemm_tc2(GArg a, GArg b) { gemm_body(blockIdx.z ? b : a); }

// split-K attention GEMM: blockIdx.z = split (K=256 each), partials to g.C
__global__ __launch_bounds__(128) void gemm_attnsp(GArg g)
{
    GArg l = g;
    int z = blockIdx.z;
    if (z < 4) { l.A0 = g.A0 + z * 256; l.aoff0 = g.aoff0; l.lda0 = g.lda0; }
    else       { l.A0 = g.A1 + (z - 4) * 256; l.aoff0 = g.aoff1; l.lda0 = g.lda1; }
    l.K0 = 256;
    l.K  = 256;
    l.Wd = g.Wd + z * 256;          // column shift within W rows (stride kw)
    l.C  = g.C + (size_t)z * BATCH * SIN;
    l.bias = nullptr;
    gemm_body(l);
}

// ---------------- fused gi-GEMM + GRU gate (grouped-N) ---------------------
#define GSROW 40
#define GIGATE_SMEM ((2*2*32*GSROW + 2*2*3*64*GSROW) * (int)sizeof(bf16))
__global__ __launch_bounds__(128) void gemm_gigate(
    const bf16* __restrict__ A, size_t aoff, int lda,
    const bf16* __restrict__ Wd, size_t woff,
    const float* __restrict__ bias,
    const float* __restrict__ gh,
    float* __restrict__ h, bf16* __restrict__ hd, int K)
{
    extern __shared__ __align__(16) bf16 dsm[];
    bf16* AsB = dsm;
    bf16* WsB = dsm + 2 * 2 * 32 * GSROW;

    const int tid = threadIdx.x, lane = tid & 31, warp = tid >> 5;
    const int wn = warp * 16;
    const int rowBase = blockIdx.y * 32, colBase = blockIdx.x * 64;

    float acc[3][2][2][4];
#pragma unroll
    for (int gg = 0; gg < 3; gg++)
#pragma unroll
        for (int mt = 0; mt < 2; mt++)
#pragma unroll
            for (int nt = 0; nt < 2; nt++)
#pragma unroll
                for (int q = 0; q < 4; q++) acc[gg][mt][nt][q] = 0.f;

    const int rA = tid >> 2, cA = (tid & 3) * 8;
    const int r1c = rA + 32;
    const int nsteps = K >> 5;

    auto As = [&](int buf, int hl) { return AsB + (buf * 2 + hl) * 32 * GSROW; };
    auto Ws = [&](int buf, int hl, int gg) { return WsB + ((buf * 2 + hl) * 3 + gg) * 64 * GSROW; };

    auto prefetch = [&](int s, int buf) {
        int k0 = s << 5;
        const bf16* pa = A + (size_t)(rowBase + rA) * lda + k0 + cA;
        cpa16((unsigned)__cvta_generic_to_shared(As(buf, 0) + rA * GSROW + cA), pa);
        cpa16((unsigned)__cvta_generic_to_shared(As(buf, 1) + rA * GSROW + cA), pa + aoff);
#pragma unroll
        for (int gg = 0; gg < 3; gg++) {
            const bf16* p0 = Wd + (size_t)(gg * 1024 + colBase + rA) * K + k0 + cA;
            const bf16* p1 = Wd + (size_t)(gg * 1024 + colBase + r1c) * K + k0 + cA;
            cpa16((unsigned)__cvta_generic_to_shared(Ws(buf, 0, gg) + rA * GSROW + cA), p0);
            cpa16((unsigned)__cvta_generic_to_shared(Ws(buf, 0, gg) + r1c * GSROW + cA), p1);
            cpa16((unsigned)__cvta_generic_to_shared(Ws(buf, 1, gg) + rA * GSROW + cA), p0 + woff);
            cpa16((unsigned)__cvta_generic_to_shared(Ws(buf, 1, gg) + r1c * GSROW + cA), p1 + woff);
        }
        asm volatile("cp.async.commit_group;");
    };

    prefetch(0, 0);

    const int aRow = lane & 15, aCol = (lane >> 4) << 3;
    const int bRow = ((lane >> 4) << 3) + (lane & 7), bCol = ((lane >> 3) & 1) << 3;

    for (int s = 0; s < nsteps; s++) {
        int buf = s & 1;
        if (s + 1 < nsteps) {
            prefetch(s + 1, buf ^ 1);
            asm volatile("cp.async.wait_group 1;");
        } else {
            asm volatile("cp.async.wait_group 0;");
        }
        __syncthreads();

#pragma unroll
        for (int hh = 0; hh < 2; hh++) {
            int kk16 = hh << 4;
            unsigned ah[2][4], al[2][4], bh[3][4], bl[3][4];
#pragma unroll
            for (int mt = 0; mt < 2; mt++) {
                int ro = (mt * 16 + aRow) * GSROW + kk16 + aCol;
                ldsm4(ah[mt], (unsigned)__cvta_generic_to_shared(As(buf, 0) + ro));
                ldsm4(al[mt], (unsigned)__cvta_generic_to_shared(As(buf, 1) + ro));
            }
#pragma unroll
            for (int gg = 0; gg < 3; gg++) {
                int ro = (wn + bRow) * GSROW + kk16 + bCol;
                ldsm4(bh[gg], (unsigned)__cvta_generic_to_shared(Ws(buf, 0, gg) + ro));
                ldsm4(bl[gg], (unsigned)__cvta_generic_to_shared(Ws(buf, 1, gg) + ro));
            }
#pragma unroll
            for (int gg = 0; gg < 3; gg++)
#pragma unroll
                for (int mt = 0; mt < 2; mt++)
#pragma unroll
                    for (int nt = 0; nt < 2; nt++) {
                        int q = nt * 2;
                        mma_bf16(acc[gg][mt][nt], ah[mt], bh[gg][q], bh[gg][q + 1]);
                        mma_bf16(acc[gg][mt][nt], ah[mt], bl[gg][q], bl[gg][q + 1]);
                        mma_bf16(acc[gg][mt][nt], al[mt], bh[gg][q], bh[gg][q + 1]);
                    }
        }
        __syncthreads();
    }

#pragma unroll
    for (int mt = 0; mt < 2; mt++)
#pragma unroll
        for (int nt = 0; nt < 2; nt++) {
            int r0 = rowBase + mt * 16 + (lane >> 2);
            int c0 = colBase + wn + nt * 8 + (lane & 3) * 2;
#pragma unroll
            for (int p = 0; p < 2; p++) {
                int r = r0 + p * 8;
                const float* ghr = gh + (size_t)r * 3072;
#pragma unroll
                for (int cc = 0; cc < 2; cc++) {
                    int c = c0 + cc;
                    float ir  = acc[0][mt][nt][p * 2 + cc] + bias[c];
                    float iz  = acc[1][mt][nt][p * 2 + cc] + bias[1024 + c];
                    float in_ = acc[2][mt][nt][p * 2 + cc] + bias[2048 + c];
                    float hr = ghr[c], hz = ghr[1024 + c], hn = ghr[2048 + c];
                    float rg = 1.f / (1.f + expf(-(ir + hr)));
                    float zg = 1.f / (1.f + expf(-(iz + hz)));
                    float ng = tanhf(in_ + rg * hn);
                    int idx = r * 1024 + c;
                    float v = (1.f - zg) * ng + zg * h[idx];
                    h[idx] = v;
                    bf16 hi, lo;
                    dec2(v, hi, lo);
                    hd[idx] = hi;
                    hd[BH + idx] = lo;
                }
            }
        }
}

// ---------------- decomposition / init ----------------
__global__ void decomp_kernel(const float* __restrict__ src, bf16* __restrict__ dst,
                              size_t off, int n)
{
    int i = blockIdx.x * 256 + threadIdx.x;
    if (i < n) {
        bf16 hi, lo;
        dec2(src[i], hi, lo);
        dst[i] = hi;
        dst[off + i] = lo;
    }
}

__global__ void init_h_kernel(const float* __restrict__ hidden,
                              float* __restrict__ h,
                              bf16* __restrict__ hd0, bf16* __restrict__ hd1init)
{
    int i = blockIdx.x * 256 + threadIdx.x;
    float v = hidden[i];
    h[i] = v;
    int l = i >> 18;
    int j = i & (BH - 1);
    bf16* hd = l ? hd1init : hd0;
    bf16 hi, lo;
    dec2(v, hi, lo);
    hd[j] = hi;
    hd[BH + j] = lo;
}

__global__ void copy_kernel(const float* __restrict__ src, float* __restrict__ dst, int n)
{
    int i = blockIdx.x * 256 + threadIdx.x;
    if (i < n) dst[i] = src[i];
}

// ---------------- fused split-reduce + softmax + wenc ----------------
__global__ void softwenc_kernel(const float* __restrict__ part,
                                const float* __restrict__ attn_b,
                                const float* __restrict__ enc,
                                float* __restrict__ out_attn, int t,
                                bf16* __restrict__ wencd)
{
    __shared__ float sm[256];
    __shared__ float a[SIN];
    int b = blockIdx.x, tid = threadIdx.x;
    float v = -1e30f;
    if (tid < SIN) {
        float s = attn_b[tid];
#pragma unroll
        for (int k = 0; k < NSPLIT; k++)
            s += part[(size_t)k * BATCH * SIN + b * SIN + tid];
        v = s;
    }
    sm[tid] = v; __syncthreads();
    for (int s = 128; s > 0; s >>= 1) {
        if (tid < s) sm[tid] = fmaxf(sm[tid], sm[tid + s]);
        __syncthreads();
    }
    float mx = sm[0]; __syncthreads();
    float e = (tid < SIN) ? expf(v - mx) : 0.f;
    sm[tid] = e; __syncthreads();
    for (int s = 128; s > 0; s >>= 1) {
        if (tid < s) sm[tid] += sm[tid + s];
        __syncthreads();
    }
    float inv = 1.f / sm[0];
    if (tid < SIN) {
        float aa = e * inv;
        a[tid] = aa;
        out_attn[(size_t)b * TOUT * SIN + (size_t)t * SIN + tid] = aa;
    }
    __syncthreads();

    const float4* ep = reinterpret_cast<const float4*>(enc + (size_t)b * SIN * HID) + tid;
    float ax = 0.f, ay = 0.f, az = 0.f, aww = 0.f;
#pragma unroll 4
    for (int s = 0; s < SIN; s++) {
        float4 vv = ep[(size_t)s * (HID / 4)];
        float w = a[s];
        ax = fmaf(w, vv.x, ax); ay = fmaf(w, vv.y, ay);
        az = fmaf(w, vv.z, az); aww = fmaf(w, vv.w, aww);
    }
    int idx = b * HID + tid * 4;
    float r4[4] = {ax, ay, az, aww};
#pragma unroll
    for (int q = 0; q < 4; q++) {
        bf16 hi, lo;
        dec2(r4[q], hi, lo);
        wencd[idx + q] = hi;
        wencd[BH + idx + q] = lo;
    }
}

// ---------------- host orchestration ----------------
extern "C" void kernel_launch(void* const* d_in, const int* in_sizes, int n_in,
                              void* d_out, int out_size)
{
    const float* target = (const float*)d_in[0];
    const float* hidden = (const float*)d_in[1];
    const float* enc    = (const float*)d_in[2];
    const float* attn_W = (const float*)d_in[3];
    const float* attn_b = (const float*)d_in[4];
    const float* comb_W = (const float*)d_in[5];
    const float* comb_b = (const float*)d_in[6];
    const float* W_ih   = (const float*)d_in[7];
    const float* W_hh   = (const float*)d_in[8];
    const float* b_ih   = (const float*)d_in[9];
    const float* b_hh   = (const float*)d_in[10];
    const float* out1_W = (const float*)d_in[11];
    const float* out1_b = (const float*)d_in[12];
    const float* out2_W = (const float*)d_in[13];
    const float* out2_b = (const float*)d_in[14];

    float* out   = (float*)d_out;
    float* out_y = out;
    float* out_h = out + (size_t)BATCH * TOUT * DIM;
    float* out_a = out_h + (size_t)NLAY * BATCH * HID;

    float *h_, *attnP, *gh0b, *gh1b;
    bf16 *hd0, *hd1, *xd, *xcd, *wencd, *tmpd;
    bf16 *attnWd, *combWd, *Wihd, *Whhd, *out1d, *out2d;
    cudaGetSymbolAddress((void**)&h_,     g_h);
    cudaGetSymbolAddress((void**)&hd0,    g_hd0);
    cudaGetSymbolAddress((void**)&hd1,    g_hd1);
    cudaGetSymbolAddress((void**)&xd,     g_xd);
    cudaGetSymbolAddress((void**)&xcd,    g_xcd);
    cudaGetSymbolAddress((void**)&wencd,  g_wencd);
    cudaGetSymbolAddress((void**)&tmpd,   g_tmpd);
    cudaGetSymbolAddress((void**)&attnP,  g_attnP);
    cudaGetSymbolAddress((void**)&gh0b,   g_gh0);
    cudaGetSymbolAddress((void**)&gh1b,   g_gh1);
    cudaGetSymbolAddress((void**)&attnWd, g_attnWd);
    cudaGetSymbolAddress((void**)&combWd, g_combWd);
    cudaGetSymbolAddress((void**)&Wihd,   g_Wihd);
    cudaGetSymbolAddress((void**)&Whhd,   g_Whhd);
    cudaGetSymbolAddress((void**)&out1d,  g_out1d);
    cudaGetSymbolAddress((void**)&out2d,  g_out2d);

    static cudaStream_t s1 = nullptr, s2 = nullptr;
    static cudaEvent_t e_g1 = nullptr, e_gh = nullptr, e_done = nullptr, e_end = nullptr;
    if (!s1) {
        int pLeast, pGreatest;
        cudaDeviceGetStreamPriorityRange(&pLeast, &pGreatest);
        cudaStreamCreateWithPriority(&s1, cudaStreamNonBlocking, pGreatest); // critical path
        cudaStreamCreateWithPriority(&s2, cudaStreamNonBlocking, pLeast);    // shadow work
        cudaEventCreateWithFlags(&e_g1,   cudaEventDisableTiming);
        cudaEventCreateWithFlags(&e_gh,   cudaEventDisableTiming);
        cudaEventCreateWithFlags(&e_done, cudaEventDisableTiming);
        cudaEventCreateWithFlags(&e_end,  cudaEventDisableTiming);
        cudaFuncSetAttribute(gemm_gigate, cudaFuncAttributeMaxDynamicSharedMemorySize,
                             GIGATE_SMEM);
    }

    // prologue on capture stream
    {
        int n;
        n = SIN * (DIM + HID);
        decomp_kernel<<<(n + 255) / 256, 256>>>(attn_W, attnWd, (size_t)SINP * (DIM + HID), n);
        n = DIM * (DIM + HID);
        decomp_kernel<<<(n + 255) / 256, 256>>>(comb_W, combWd, n, n);
        n = NLAY * 3 * HID * DIM;
        decomp_kernel<<<(n + 255) / 256, 256>>>(W_ih, Wihd, n, n);
        n = NLAY * 3 * HID * HID;
        decomp_kernel<<<(n + 255) / 256, 256>>>(W_hh, Whhd, n, n);
        n = DIM * HID;
        decomp_kernel<<<(n + 255) / 256, 256>>>(out1_W, out1d, n, n);
        n = DIM * DIM;
        decomp_kernel<<<(n + 255) / 256, 256>>>(out2_W, out2d, n, n);
        n = (int)(BATCH * TOUT * DIM);
        decomp_kernel<<<(n + 255) / 256, 256>>>(target, xd, XOFF, n);
        init_h_kernel<<<(NLAY * BH) / 256, 256>>>(hidden, h_, hd0, hd1 + PAR);
    }
    cudaEventRecord(e_g1, 0);
    cudaStreamWaitEvent(s1, e_g1, 0);   // fork both worker streams off prologue

    const int LDX = TOUT * DIM;
    const size_t BD = (size_t)BATCH * DIM;

    for (int t = 0; t < TOUT; t++) {
        bf16* hd1_rd = hd1 + ((t - 1) & 1) * (size_t)PAR;
        bf16* hd1_wr = hd1 + (t & 1) * (size_t)PAR;
        const bf16* xt = xd + (size_t)t * DIM;

        // ---- s2 (low prio): gh pair for step t, then out-head for t-1 ----
        cudaStreamWaitEvent(s2, e_g1, 0);
        GArg gh0a = { hd0, BH, HID, HID, nullptr, 0, 0,
                      Whhd, WHH_OFF, b_hh, gh0b, 3 * HID,
                      nullptr, 0, 0, 3 * HID, HID, HID, 0 };
        GArg gh1a = { hd1_rd, BH, HID, HID, nullptr, 0, 0,
                      Whhd + (size_t)3 * HID * HID, WHH_OFF, b_hh + 3 * HID,
                      gh1b, 3 * HID, nullptr, 0, 0, 3 * HID, HID, HID, 0 };
        gemm_tc2<<<dim3(48, 4, 2), 128, 0, s2>>>(gh0a, gh1a);
        cudaEventRecord(e_gh, s2);
        if (t > 0) {
            bf16* hprev = hd1 + ((t - 1) & 1) * (size_t)PAR;
            GArg go1 = { hprev, BH, HID, HID, nullptr, 0, 0,
                         out1d, (size_t)DIM * HID, out1_b,
                         nullptr, 0, tmpd, BD, DIM, DIM, HID, HID, 0 };
            gemm_tc<<<dim3(16, 4), 128, 0, s2>>>(go1);
            GArg go2 = { tmpd, BD, DIM, DIM, nullptr, 0, 0,
                         out2d, (size_t)DIM * DIM, out2_b,
                         out_y + (size_t)(t - 1) * DIM, LDX,
                         nullptr, 0, 0, DIM, DIM, DIM, 0 };
            gemm_tc<<<dim3(16, 4), 128, 0, s2>>>(go2);
        }

        // ---- s1 (high prio): attn(split-K) -> softwenc -> comb -> gigate x2
        GArg ga = { xt, XOFF, LDX, DIM, hd1_rd, BH, HID,
                    attnWd, (size_t)SINP * (DIM + HID), nullptr,
                    attnP, SIN, nullptr, 0, 0, SIN, DIM + HID, DIM + HID, 0 };
        gemm_attnsp<<<dim3(2, 4, NSPLIT), 128, 0, s1>>>(ga);
        softwenc_kernel<<<BATCH, 256, 0, s1>>>(attnP, attn_b, enc, out_a, t, wencd);

        GArg gc = { xt, XOFF, LDX, DIM, wencd, BH, HID,
                    combWd, (size_t)DIM * (DIM + HID), comb_b,
                    nullptr, 0, xcd, BD, DIM, DIM, DIM + HID, DIM + HID, 1 };
        gemm_tc<<<dim3(16, 4), 128, 0, s1>>>(gc);

        cudaStreamWaitEvent(s1, e_gh, 0);
        gemm_gigate<<<dim3(16, 8), 128, GIGATE_SMEM, s1>>>(
            xcd, BD, DIM, Wihd, WIH_OFF, b_ih, gh0b, h_, hd0, DIM);
        gemm_gigate<<<dim3(16, 8), 128, GIGATE_SMEM, s1>>>(
            hd0, BH, HID, Wihd + (size_t)3 * HID * DIM, WIH_OFF,
            b_ih + 3 * HID, gh1b, h_ + BH, hd1_wr, HID);
        cudaEventRecord(e_g1, s1);
    }

    // tail: out-head for t=35 on s2, join via s1, final hidden copy
    cudaStreamWaitEvent(s2, e_g1, 0);
    {
        bf16* hlast = hd1 + ((TOUT - 1) & 1) * (size_t)PAR;
        GArg go1 = { hlast, BH, HID, HID, nullptr, 0, 0,
                     out1d, (size_t)DIM * HID, out1_b,
                     nullptr, 0, tmpd, BD, DIM, DIM, HID, HID, 0 };
        gemm_tc<<<dim3(16, 4), 128, 0, s2>>>(go1);
        GArg go2 = { tmpd, BD, DIM, DIM, nullptr, 0, 0,
                     out2d, (size_t)DIM * DIM, out2_b,
                     out_y + (size_t)(TOUT - 1) * DIM, LDX,
                     nullptr, 0, 0, DIM, DIM, DIM, 0 };
        gemm_tc<<<dim3(16, 4), 128, 0, s2>>>(go2);
    }
    cudaEventRecord(e_done, s2);
    cudaStreamWaitEvent(s1, e_done, 0);
    copy_kernel<<<(NLAY * BH) / 256, 256, 0, s1>>>(h_, out_h, NLAY * BH);
    cudaEventRecord(e_end, s1);
    cudaStreamWaitEvent(0, e_end, 0);
}